// round 2
// baseline (speedup 1.0000x reference)
#include <cuda_runtime.h>
#include <cuda_bf16.h>

// Problem constants (fixed by the reference)
#define S_IN   44
#define HID    128
#define DD     64      // embedding dim
#define VV     16      // vector channels
#define HH     16      // hidden vector channels
#define NRBF   16
#define NEF    16
#define XW     112     // GEMV input width: 64 + 16 + 16 + 16
#define VCIN   17      // V + 1
#define NN     50000
#define NE     800000
#define NLAYER 3
#define DMAX_F 10.0f

// -------- device scratch (static: no allocation allowed) --------
__device__ float g_s[NN * DD];        // current scalar features
__device__ float g_v[NN * VV * 3];    // current vector features
__device__ float g_aggs[NN * DD];     // per-layer scalar aggregation
__device__ float g_aggv[NN * VV * 3]; // per-layer vector aggregation
__device__ float g_deg[NN];
__device__ float g_invdeg[NN];

// ---------------------------------------------------------------
// Node embedding: s = relu(sf @ W1 + b1) @ W2 + b2, plus v init copy.
// 8 nodes per block of 128 threads (amortizes W1/W2 reads 8x).
// ---------------------------------------------------------------
__global__ __launch_bounds__(128) void embed_kernel(
    const float* __restrict__ sf, const float* __restrict__ W1,
    const float* __restrict__ b1, const float* __restrict__ W2,
    const float* __restrict__ b2, const float* __restrict__ vf)
{
    __shared__ float ssf[8][S_IN];
    __shared__ float sh[8][HID];
    const int nb = blockIdx.x * 8;
    const int t  = threadIdx.x;

    for (int i = t; i < 8 * S_IN; i += 128) {
        int n = i / S_IN, k = i - n * S_IN;
        int node = nb + n;
        ssf[n][k] = (node < NN) ? sf[node * S_IN + k] : 0.f;
    }
    __syncthreads();

    // hidden layer: thread t owns hidden unit t for all 8 nodes
    float acc[8];
    float bb = b1[t];
#pragma unroll
    for (int n = 0; n < 8; n++) acc[n] = bb;
    for (int k = 0; k < S_IN; k++) {
        float w = W1[k * HID + t];
#pragma unroll
        for (int n = 0; n < 8; n++) acc[n] += ssf[n][k] * w;
    }
#pragma unroll
    for (int n = 0; n < 8; n++) sh[n][t] = fmaxf(acc[n], 0.f);
    __syncthreads();

    if (t < DD) {
        float acc2[8];
        float b2v = b2[t];
#pragma unroll
        for (int n = 0; n < 8; n++) acc2[n] = b2v;
        for (int k = 0; k < HID; k++) {
            float w = W2[k * DD + t];
#pragma unroll
            for (int n = 0; n < 8; n++) acc2[n] += sh[n][k] * w;
        }
#pragma unroll
        for (int n = 0; n < 8; n++)
            if (nb + n < NN) g_s[(nb + n) * DD + t] = acc2[n];
    }

    // copy vector features into working buffer
    for (int i = t; i < 8 * VV * 3; i += 128) {
        int n = i / (VV * 3), k = i - n * (VV * 3);
        int node = nb + n;
        if (node < NN) g_v[node * VV * 3 + k] = vf[node * VV * 3 + k];
    }
}

__global__ void deg_kernel(const int* __restrict__ ei)
{
    int e = blockIdx.x * blockDim.x + threadIdx.x;
    if (e < NE) atomicAdd(&g_deg[ei[NE + e]], 1.0f);
}

__global__ void invdeg_kernel()
{
    int i = blockIdx.x * blockDim.x + threadIdx.x;
    if (i < NN) g_invdeg[i] = 1.0f / fmaxf(g_deg[i], 1.0f);
}

// ---------------------------------------------------------------
// Edge message kernel (one GVP layer). Warp processes 4 edges.
// Per-edge scratch (224 floats): X[0:112] | Vh[112:160] | U[160:224]
//   U holds vin (51) first, then is reused for SM (64).
//   X[96:112] holds vnorm during GEMV, then is reused for gate.
// ---------------------------------------------------------------
#define EPW 4                 // edges per warp
#define SCR_PER_EDGE 224
#define NWARP 8               // 256 threads
// float offsets inside dynamic smem
#define OFF_WS   0
#define OFF_WH   (OFF_WS  + XW * DD)      // 7168
#define OFF_WMU  (OFF_WH  + VCIN * HH)    // +272
#define OFF_WG   (OFF_WMU + HH * VV)      // +256
#define OFF_BS   (OFF_WG  + DD * VV)      // +1024
#define OFF_BG   (OFF_BS  + DD)           // +64
#define OFF_SCR  (OFF_BG  + VV)           // +16
#define SMEM_FLOATS (OFF_SCR + NWARP * EPW * SCR_PER_EDGE)
#define SMEM_BYTES  (SMEM_FLOATS * 4)

__global__ __launch_bounds__(256) void edge_kernel(
    const float* __restrict__ ef, const float* __restrict__ xd,
    const float* __restrict__ dvec, const int* __restrict__ ei,
    const float* __restrict__ Wh, const float* __restrict__ Ws,
    const float* __restrict__ bs, const float* __restrict__ Wmu,
    const float* __restrict__ Wg, const float* __restrict__ bg)
{
    extern __shared__ float smem[];
    float* sWs  = smem + OFF_WS;
    float* sWh  = smem + OFF_WH;
    float* sWmu = smem + OFF_WMU;
    float* sWg  = smem + OFF_WG;
    float* sbs  = smem + OFF_BS;
    float* sbg  = smem + OFF_BG;

    const int t = threadIdx.x;
    for (int i = t; i < XW * DD; i += 256) sWs[i]  = Ws[i];
    for (int i = t; i < VCIN * HH; i += 256) sWh[i]  = Wh[i];
    for (int i = t; i < HH * VV; i += 256) sWmu[i] = Wmu[i];
    for (int i = t; i < DD * VV; i += 256) sWg[i]  = Wg[i];
    if (t < DD) sbs[t] = bs[t];
    if (t < VV) sbg[t] = bg[t];
    __syncthreads();

    const int warp = t >> 5, lane = t & 31;
    float* scr = smem + OFF_SCR + warp * EPW * SCR_PER_EDGE;

    const float inv_sigma = (float)NRBF / DMAX_F;       // 1/sigma
    const float mu_step   = DMAX_F / (float)(NRBF - 1); // linspace step

    const int ntiles = (NE + NWARP * EPW - 1) / (NWARP * EPW);
    for (int tile = blockIdx.x; tile < ntiles; tile += gridDim.x) {
        const int ebase = tile * (NWARP * EPW) + warp * EPW;
        int dsts[EPW];

        // ---- Phase 1: assemble X (s | rbf | ef | .) and vin ----
#pragma unroll
        for (int q = 0; q < EPW; q++) {
            const int e = ebase + q;
            float* X = scr + q * SCR_PER_EDGE;
            float* U = X + 160;
            if (e < NE) {
                const int src = ei[e];
                dsts[q] = ei[NE + e];
                X[lane]      = g_s[src * DD + lane];
                X[lane + 32] = g_s[src * DD + 32 + lane];
                if (lane < 16) {
                    float de = dvec[e];
                    float tt = (de - (float)lane * mu_step) * inv_sigma;
                    X[64 + lane] = __expf(-tt * tt);
                    X[80 + lane] = ef[e * NEF + lane];
                }
                U[lane] = g_v[src * 48 + lane];        // lanes 0..31 (<48)
                if (lane < 19) {
                    int idx = 32 + lane;
                    U[idx] = (idx < 48) ? g_v[src * 48 + idx]
                                        : xd[e * 3 + (idx - 48)];
                }
            } else {
                dsts[q] = -1;
            }
        }
        __syncwarp();

        // ---- Phase 2: Vh[h,d] = sum_c vin[c,d]*Wh[c,h] ----
#pragma unroll
        for (int q = 0; q < EPW; q++) {
            if (dsts[q] < 0) continue;
            float* X   = scr + q * SCR_PER_EDGE;
            float* Vh  = X + 112;
            float* vin = X + 160;
            {
                int i = lane, h = i / 3, dd = i - h * 3;
                float a = 0.f;
#pragma unroll
                for (int c = 0; c < VCIN; c++) a += vin[c * 3 + dd] * sWh[c * HH + h];
                Vh[i] = a;
            }
            if (lane < 16) {
                int i = lane + 32, h = i / 3, dd = i - h * 3;
                float a = 0.f;
#pragma unroll
                for (int c = 0; c < VCIN; c++) a += vin[c * 3 + dd] * sWh[c * HH + h];
                Vh[i] = a;
            }
        }
        __syncwarp();

        // ---- Phase 2b: vnorm into X[96:112] ----
#pragma unroll
        for (int q = 0; q < EPW; q++) {
            if (dsts[q] < 0) continue;
            float* X  = scr + q * SCR_PER_EDGE;
            float* Vh = X + 112;
            if (lane < 16) {
                float a = Vh[lane * 3], b = Vh[lane * 3 + 1], c = Vh[lane * 3 + 2];
                X[96 + lane] = sqrtf(a * a + b * b + c * c + 1e-8f);
            }
        }
        __syncwarp();

        // ---- Phase 3: sm = relu(X @ Ws + bs), 4 edges jointly ----
        const int j0 = 2 * lane;
        float acc[EPW][2];
#pragma unroll
        for (int q = 0; q < EPW; q++) { acc[q][0] = sbs[j0]; acc[q][1] = sbs[j0 + 1]; }
        {
            const float* X0 = scr;
            const float* X1 = scr + SCR_PER_EDGE;
            const float* X2 = scr + 2 * SCR_PER_EDGE;
            const float* X3 = scr + 3 * SCR_PER_EDGE;
#pragma unroll
            for (int k = 0; k < XW; k += 4) {
                float4 x0 = *(const float4*)(X0 + k);
                float4 x1 = *(const float4*)(X1 + k);
                float4 x2 = *(const float4*)(X2 + k);
                float4 x3 = *(const float4*)(X3 + k);
#pragma unroll
                for (int kk = 0; kk < 4; kk++) {
                    float2 w = *(const float2*)&sWs[(k + kk) * DD + j0];
                    float a0 = ((const float*)&x0)[kk];
                    float a1 = ((const float*)&x1)[kk];
                    float a2 = ((const float*)&x2)[kk];
                    float a3 = ((const float*)&x3)[kk];
                    acc[0][0] += a0 * w.x; acc[0][1] += a0 * w.y;
                    acc[1][0] += a1 * w.x; acc[1][1] += a1 * w.y;
                    acc[2][0] += a2 * w.x; acc[2][1] += a2 * w.y;
                    acc[3][0] += a3 * w.x; acc[3][1] += a3 * w.y;
                }
            }
        }
#pragma unroll
        for (int q = 0; q < EPW; q++) {
            if (dsts[q] < 0) continue;
            float s0 = fmaxf(acc[q][0], 0.f);
            float s1 = fmaxf(acc[q][1], 0.f);
            float* SM = scr + q * SCR_PER_EDGE + 160; // reuse vin space
            SM[j0] = s0; SM[j0 + 1] = s1;
            atomicAdd(&g_aggs[dsts[q] * DD + j0],     s0);
            atomicAdd(&g_aggs[dsts[q] * DD + j0 + 1], s1);
        }
        __syncwarp();

        // ---- Phase 4: gate = sigmoid(sm @ Wg + bg), into X[96:112] ----
#pragma unroll
        for (int q = 0; q < EPW; q++) {
            if (dsts[q] < 0) continue;
            float* X  = scr + q * SCR_PER_EDGE;
            float* SM = X + 160;
            if (lane < VV) {
                float a = sbg[lane];
#pragma unroll 8
                for (int j = 0; j < DD; j++) a += SM[j] * sWg[j * VV + lane];
                X[96 + lane] = 1.f / (1.f + __expf(-a));
            }
        }
        __syncwarp();

        // ---- Phase 5: vm = (Vh @ Wmu) * gate, scatter ----
#pragma unroll
        for (int q = 0; q < EPW; q++) {
            if (dsts[q] < 0) continue;
            float* X  = scr + q * SCR_PER_EDGE;
            float* Vh = X + 112;
            {
                int i = lane, o = i / 3, dd = i - o * 3;
                float a = 0.f;
#pragma unroll
                for (int h = 0; h < HH; h++) a += Vh[h * 3 + dd] * sWmu[h * VV + o];
                atomicAdd(&g_aggv[dsts[q] * 48 + i], a * X[96 + o]);
            }
            if (lane < 16) {
                int i = lane + 32, o = i / 3, dd = i - o * 3;
                float a = 0.f;
#pragma unroll
                for (int h = 0; h < HH; h++) a += Vh[h * 3 + dd] * sWmu[h * VV + o];
                atomicAdd(&g_aggv[dsts[q] * 48 + i], a * X[96 + o]);
            }
        }
        __syncwarp();
    }
}

// ---------------------------------------------------------------
// Residual mean-aggregate update. First NN*DD threads -> s,
// next NN*48 -> v. Last layer also writes s to d_out.
// ---------------------------------------------------------------
__global__ void update_kernel(float* __restrict__ out)
{
    int i = blockIdx.x * blockDim.x + threadIdx.x;
    if (i < NN * DD) {
        float val = g_s[i] + g_aggs[i] * g_invdeg[i >> 6];
        g_s[i] = val;
        if (out) out[i] = val;
    } else {
        int j = i - NN * DD;
        if (j < NN * 48) g_v[j] += g_aggv[j] * g_invdeg[j / 48];
    }
}

// ---------------------------------------------------------------
extern "C" void kernel_launch(void* const* d_in, const int* in_sizes, int n_in,
                              void* d_out, int out_size)
{
    const float* sf  = (const float*)d_in[0];
    // d_in[1] = coord_feats (unused by reference output path)
    const float* vf  = (const float*)d_in[2];
    const float* ef  = (const float*)d_in[3];
    const float* xd  = (const float*)d_in[4];
    const float* dv  = (const float*)d_in[5];
    const int*   eix = (const int*)  d_in[6];
    const float* W1  = (const float*)d_in[7];
    const float* b1  = (const float*)d_in[8];
    const float* W2  = (const float*)d_in[9];
    const float* b2  = (const float*)d_in[10];
    const float* Wh  = (const float*)d_in[11];
    const float* Ws  = (const float*)d_in[12];
    const float* bs  = (const float*)d_in[13];
    const float* Wmu = (const float*)d_in[14];
    const float* Wg  = (const float*)d_in[15];
    const float* bg  = (const float*)d_in[16];

    (void)in_sizes; (void)n_in; (void)out_size;

    cudaFuncSetAttribute(edge_kernel,
                         cudaFuncAttributeMaxDynamicSharedMemorySize, SMEM_BYTES);

    void *p_deg = nullptr, *p_aggs = nullptr, *p_aggv = nullptr;
    cudaGetSymbolAddress(&p_deg,  g_deg);
    cudaGetSymbolAddress(&p_aggs, g_aggs);
    cudaGetSymbolAddress(&p_aggv, g_aggv);

    // node embedding + v init
    embed_kernel<<<(NN + 7) / 8, 128>>>(sf, W1, b1, W2, b2, vf);

    // degrees (recomputed every replay: memset then count)
    cudaMemsetAsync(p_deg, 0, NN * sizeof(float));
    deg_kernel<<<(NE + 255) / 256, 256>>>(eix);
    invdeg_kernel<<<(NN + 255) / 256, 256>>>();

    const int upd_threads = NN * DD + NN * 48;
    for (int l = 0; l < NLAYER; l++) {
        cudaMemsetAsync(p_aggs, 0, (size_t)NN * DD * sizeof(float));
        cudaMemsetAsync(p_aggv, 0, (size_t)NN * 48 * sizeof(float));
        edge_kernel<<<444, 256, SMEM_BYTES>>>(
            ef, xd, dv, eix,
            Wh  + l * VCIN * HH,
            Ws  + l * XW * DD,
            bs  + l * DD,
            Wmu + l * HH * VV,
            Wg  + l * DD * VV,
            bg  + l * VV);
        update_kernel<<<(upd_threads + 255) / 256, 256>>>(
            (l == NLAYER - 1) ? (float*)d_out : nullptr);
    }
}

// round 3
// speedup vs baseline: 1.0037x; 1.0037x over previous
#include <cuda_runtime.h>
#include <cuda_bf16.h>

// Problem constants (fixed by the reference)
#define S_IN   44
#define HID    128
#define DD     64      // embedding dim
#define VV     16      // vector channels
#define HH     16      // hidden vector channels
#define NRBF   16
#define NEF    16
#define XW     112     // GEMV input width: 64 + 16 + 16 + 16
#define VCIN   17      // V + 1
#define NN     50000
#define NE     800000
#define NLAYER 3
#define DMAX_F 10.0f

// -------- device scratch (static: no allocation allowed) --------
__device__ float g_s[NN * DD];        // current scalar features
__device__ float g_v[NN * VV * 3];    // current vector features
__device__ float g_aggs[NN * DD];     // per-layer scalar aggregation
__device__ float g_aggv[NN * VV * 3]; // per-layer vector aggregation
__device__ float g_deg[NN];
__device__ float g_invdeg[NN];

// ---------------------------------------------------------------
// Node embedding: s = relu(sf @ W1 + b1) @ W2 + b2, plus v init copy.
// 8 nodes per block of 128 threads (amortizes W1/W2 reads 8x).
// ---------------------------------------------------------------
__global__ __launch_bounds__(128) void embed_kernel(
    const float* __restrict__ sf, const float* __restrict__ W1,
    const float* __restrict__ b1, const float* __restrict__ W2,
    const float* __restrict__ b2, const float* __restrict__ vf)
{
    __shared__ float ssf[8][S_IN];
    __shared__ float sh[8][HID];
    const int nb = blockIdx.x * 8;
    const int t  = threadIdx.x;

    for (int i = t; i < 8 * S_IN; i += 128) {
        int n = i / S_IN, k = i - n * S_IN;
        int node = nb + n;
        ssf[n][k] = (node < NN) ? sf[node * S_IN + k] : 0.f;
    }
    __syncthreads();

    // hidden layer: thread t owns hidden unit t for all 8 nodes
    float acc[8];
    float bb = b1[t];
#pragma unroll
    for (int n = 0; n < 8; n++) acc[n] = bb;
    for (int k = 0; k < S_IN; k++) {
        float w = W1[k * HID + t];
#pragma unroll
        for (int n = 0; n < 8; n++) acc[n] += ssf[n][k] * w;
    }
#pragma unroll
    for (int n = 0; n < 8; n++) sh[n][t] = fmaxf(acc[n], 0.f);
    __syncthreads();

    if (t < DD) {
        float acc2[8];
        float b2v = b2[t];
#pragma unroll
        for (int n = 0; n < 8; n++) acc2[n] = b2v;
        for (int k = 0; k < HID; k++) {
            float w = W2[k * DD + t];
#pragma unroll
            for (int n = 0; n < 8; n++) acc2[n] += sh[n][k] * w;
        }
#pragma unroll
        for (int n = 0; n < 8; n++)
            if (nb + n < NN) g_s[(nb + n) * DD + t] = acc2[n];
    }

    // copy vector features into working buffer
    for (int i = t; i < 8 * VV * 3; i += 128) {
        int n = i / (VV * 3), k = i - n * (VV * 3);
        int node = nb + n;
        if (node < NN) g_v[node * VV * 3 + k] = vf[node * VV * 3 + k];
    }
}

__global__ void deg_kernel(const int* __restrict__ ei)
{
    int e = blockIdx.x * blockDim.x + threadIdx.x;
    if (e < NE) atomicAdd(&g_deg[ei[NE + e]], 1.0f);
}

__global__ void invdeg_kernel()
{
    int i = blockIdx.x * blockDim.x + threadIdx.x;
    if (i < NN) g_invdeg[i] = 1.0f / fmaxf(g_deg[i], 1.0f);
}

// ---------------------------------------------------------------
// Edge message kernel (one GVP layer). Warp processes 4 edges.
// Per-edge scratch (224 floats): X[0:112] | Vh[112:160] | U[160:224]
//   U holds vin (51) first, then is reused for SM (64).
//   X[96:112] holds vnorm during GEMV, then is reused for gate.
// ---------------------------------------------------------------
#define EPW 4                 // edges per warp
#define SCR_PER_EDGE 224
#define NWARP 8               // 256 threads
// float offsets inside dynamic smem
#define OFF_WS   0
#define OFF_WH   (OFF_WS  + XW * DD)      // 7168
#define OFF_WMU  (OFF_WH  + VCIN * HH)    // +272
#define OFF_WG   (OFF_WMU + HH * VV)      // +256
#define OFF_BS   (OFF_WG  + DD * VV)      // +1024
#define OFF_BG   (OFF_BS  + DD)           // +64
#define OFF_SCR  (OFF_BG  + VV)           // +16
#define SMEM_FLOATS (OFF_SCR + NWARP * EPW * SCR_PER_EDGE)
#define SMEM_BYTES  (SMEM_FLOATS * 4)

__global__ __launch_bounds__(256) void edge_kernel(
    const float* __restrict__ ef, const float* __restrict__ xd,
    const float* __restrict__ dvec, const int* __restrict__ ei,
    const float* __restrict__ Wh, const float* __restrict__ Ws,
    const float* __restrict__ bs, const float* __restrict__ Wmu,
    const float* __restrict__ Wg, const float* __restrict__ bg)
{
    extern __shared__ float smem[];
    float* sWs  = smem + OFF_WS;
    float* sWh  = smem + OFF_WH;
    float* sWmu = smem + OFF_WMU;
    float* sWg  = smem + OFF_WG;
    float* sbs  = smem + OFF_BS;
    float* sbg  = smem + OFF_BG;

    const int t = threadIdx.x;
    for (int i = t; i < XW * DD; i += 256) sWs[i]  = Ws[i];
    for (int i = t; i < VCIN * HH; i += 256) sWh[i]  = Wh[i];
    for (int i = t; i < HH * VV; i += 256) sWmu[i] = Wmu[i];
    for (int i = t; i < DD * VV; i += 256) sWg[i]  = Wg[i];
    if (t < DD) sbs[t] = bs[t];
    if (t < VV) sbg[t] = bg[t];
    __syncthreads();

    const int warp = t >> 5, lane = t & 31;
    float* scr = smem + OFF_SCR + warp * EPW * SCR_PER_EDGE;

    const float inv_sigma = (float)NRBF / DMAX_F;       // 1/sigma
    const float mu_step   = DMAX_F / (float)(NRBF - 1); // linspace step

    const int ntiles = (NE + NWARP * EPW - 1) / (NWARP * EPW);
    for (int tile = blockIdx.x; tile < ntiles; tile += gridDim.x) {
        const int ebase = tile * (NWARP * EPW) + warp * EPW;
        int dsts[EPW];

        // ---- Phase 1: assemble X (s | rbf | ef | .) and vin ----
#pragma unroll
        for (int q = 0; q < EPW; q++) {
            const int e = ebase + q;
            float* X = scr + q * SCR_PER_EDGE;
            float* U = X + 160;
            if (e < NE) {
                const int src = ei[e];
                dsts[q] = ei[NE + e];
                X[lane]      = g_s[src * DD + lane];
                X[lane + 32] = g_s[src * DD + 32 + lane];
                if (lane < 16) {
                    float de = dvec[e];
                    float tt = (de - (float)lane * mu_step) * inv_sigma;
                    X[64 + lane] = __expf(-tt * tt);
                    X[80 + lane] = ef[e * NEF + lane];
                }
                U[lane] = g_v[src * 48 + lane];        // lanes 0..31 (<48)
                if (lane < 19) {
                    int idx = 32 + lane;
                    U[idx] = (idx < 48) ? g_v[src * 48 + idx]
                                        : xd[e * 3 + (idx - 48)];
                }
            } else {
                dsts[q] = -1;
            }
        }
        __syncwarp();

        // ---- Phase 2: Vh[h,d] = sum_c vin[c,d]*Wh[c,h] ----
#pragma unroll
        for (int q = 0; q < EPW; q++) {
            if (dsts[q] < 0) continue;
            float* X   = scr + q * SCR_PER_EDGE;
            float* Vh  = X + 112;
            float* vin = X + 160;
            {
                int i = lane, h = i / 3, dd = i - h * 3;
                float a = 0.f;
#pragma unroll
                for (int c = 0; c < VCIN; c++) a += vin[c * 3 + dd] * sWh[c * HH + h];
                Vh[i] = a;
            }
            if (lane < 16) {
                int i = lane + 32, h = i / 3, dd = i - h * 3;
                float a = 0.f;
#pragma unroll
                for (int c = 0; c < VCIN; c++) a += vin[c * 3 + dd] * sWh[c * HH + h];
                Vh[i] = a;
            }
        }
        __syncwarp();

        // ---- Phase 2b: vnorm into X[96:112] ----
#pragma unroll
        for (int q = 0; q < EPW; q++) {
            if (dsts[q] < 0) continue;
            float* X  = scr + q * SCR_PER_EDGE;
            float* Vh = X + 112;
            if (lane < 16) {
                float a = Vh[lane * 3], b = Vh[lane * 3 + 1], c = Vh[lane * 3 + 2];
                X[96 + lane] = sqrtf(a * a + b * b + c * c + 1e-8f);
            }
        }
        __syncwarp();

        // ---- Phase 3: sm = relu(X @ Ws + bs), 4 edges jointly ----
        const int j0 = 2 * lane;
        float acc[EPW][2];
#pragma unroll
        for (int q = 0; q < EPW; q++) { acc[q][0] = sbs[j0]; acc[q][1] = sbs[j0 + 1]; }
        {
            const float* X0 = scr;
            const float* X1 = scr + SCR_PER_EDGE;
            const float* X2 = scr + 2 * SCR_PER_EDGE;
            const float* X3 = scr + 3 * SCR_PER_EDGE;
#pragma unroll
            for (int k = 0; k < XW; k += 4) {
                float4 x0 = *(const float4*)(X0 + k);
                float4 x1 = *(const float4*)(X1 + k);
                float4 x2 = *(const float4*)(X2 + k);
                float4 x3 = *(const float4*)(X3 + k);
#pragma unroll
                for (int kk = 0; kk < 4; kk++) {
                    float2 w = *(const float2*)&sWs[(k + kk) * DD + j0];
                    float a0 = ((const float*)&x0)[kk];
                    float a1 = ((const float*)&x1)[kk];
                    float a2 = ((const float*)&x2)[kk];
                    float a3 = ((const float*)&x3)[kk];
                    acc[0][0] += a0 * w.x; acc[0][1] += a0 * w.y;
                    acc[1][0] += a1 * w.x; acc[1][1] += a1 * w.y;
                    acc[2][0] += a2 * w.x; acc[2][1] += a2 * w.y;
                    acc[3][0] += a3 * w.x; acc[3][1] += a3 * w.y;
                }
            }
        }
#pragma unroll
        for (int q = 0; q < EPW; q++) {
            if (dsts[q] < 0) continue;
            float s0 = fmaxf(acc[q][0], 0.f);
            float s1 = fmaxf(acc[q][1], 0.f);
            float* SM = scr + q * SCR_PER_EDGE + 160; // reuse vin space
            SM[j0] = s0; SM[j0 + 1] = s1;
            atomicAdd(&g_aggs[dsts[q] * DD + j0],     s0);
            atomicAdd(&g_aggs[dsts[q] * DD + j0 + 1], s1);
        }
        __syncwarp();

        // ---- Phase 4: gate = sigmoid(sm @ Wg + bg), into X[96:112] ----
#pragma unroll
        for (int q = 0; q < EPW; q++) {
            if (dsts[q] < 0) continue;
            float* X  = scr + q * SCR_PER_EDGE;
            float* SM = X + 160;
            if (lane < VV) {
                float a = sbg[lane];
#pragma unroll 8
                for (int j = 0; j < DD; j++) a += SM[j] * sWg[j * VV + lane];
                X[96 + lane] = 1.f / (1.f + __expf(-a));
            }
        }
        __syncwarp();

        // ---- Phase 5: vm = (Vh @ Wmu) * gate, scatter ----
#pragma unroll
        for (int q = 0; q < EPW; q++) {
            if (dsts[q] < 0) continue;
            float* X  = scr + q * SCR_PER_EDGE;
            float* Vh = X + 112;
            {
                int i = lane, o = i / 3, dd = i - o * 3;
                float a = 0.f;
#pragma unroll
                for (int h = 0; h < HH; h++) a += Vh[h * 3 + dd] * sWmu[h * VV + o];
                atomicAdd(&g_aggv[dsts[q] * 48 + i], a * X[96 + o]);
            }
            if (lane < 16) {
                int i = lane + 32, o = i / 3, dd = i - o * 3;
                float a = 0.f;
#pragma unroll
                for (int h = 0; h < HH; h++) a += Vh[h * 3 + dd] * sWmu[h * VV + o];
                atomicAdd(&g_aggv[dsts[q] * 48 + i], a * X[96 + o]);
            }
        }
        __syncwarp();
    }
}

// ---------------------------------------------------------------
// Residual mean-aggregate update. First NN*DD threads -> s,
// next NN*48 -> v. Last layer also writes s to d_out.
// ---------------------------------------------------------------
__global__ void update_kernel(float* __restrict__ out)
{
    int i = blockIdx.x * blockDim.x + threadIdx.x;
    if (i < NN * DD) {
        float val = g_s[i] + g_aggs[i] * g_invdeg[i >> 6];
        g_s[i] = val;
        if (out) out[i] = val;
    } else {
        int j = i - NN * DD;
        if (j < NN * 48) g_v[j] += g_aggv[j] * g_invdeg[j / 48];
    }
}

// ---------------------------------------------------------------
extern "C" void kernel_launch(void* const* d_in, const int* in_sizes, int n_in,
                              void* d_out, int out_size)
{
    const float* sf  = (const float*)d_in[0];
    // d_in[1] = coord_feats (unused by reference output path)
    const float* vf  = (const float*)d_in[2];
    const float* ef  = (const float*)d_in[3];
    const float* xd  = (const float*)d_in[4];
    const float* dv  = (const float*)d_in[5];
    const int*   eix = (const int*)  d_in[6];
    const float* W1  = (const float*)d_in[7];
    const float* b1  = (const float*)d_in[8];
    const float* W2  = (const float*)d_in[9];
    const float* b2  = (const float*)d_in[10];
    const float* Wh  = (const float*)d_in[11];
    const float* Ws  = (const float*)d_in[12];
    const float* bs  = (const float*)d_in[13];
    const float* Wmu = (const float*)d_in[14];
    const float* Wg  = (const float*)d_in[15];
    const float* bg  = (const float*)d_in[16];

    (void)in_sizes; (void)n_in; (void)out_size;

    cudaFuncSetAttribute(edge_kernel,
                         cudaFuncAttributeMaxDynamicSharedMemorySize, SMEM_BYTES);

    void *p_deg = nullptr, *p_aggs = nullptr, *p_aggv = nullptr;
    cudaGetSymbolAddress(&p_deg,  g_deg);
    cudaGetSymbolAddress(&p_aggs, g_aggs);
    cudaGetSymbolAddress(&p_aggv, g_aggv);

    // node embedding + v init
    embed_kernel<<<(NN + 7) / 8, 128>>>(sf, W1, b1, W2, b2, vf);

    // degrees (recomputed every replay: memset then count)
    cudaMemsetAsync(p_deg, 0, NN * sizeof(float));
    deg_kernel<<<(NE + 255) / 256, 256>>>(eix);
    invdeg_kernel<<<(NN + 255) / 256, 256>>>();

    const int upd_threads = NN * DD + NN * 48;
    for (int l = 0; l < NLAYER; l++) {
        cudaMemsetAsync(p_aggs, 0, (size_t)NN * DD * sizeof(float));
        cudaMemsetAsync(p_aggv, 0, (size_t)NN * 48 * sizeof(float));
        edge_kernel<<<444, 256, SMEM_BYTES>>>(
            ef, xd, dv, eix,
            Wh  + l * VCIN * HH,
            Ws  + l * XW * DD,
            bs  + l * DD,
            Wmu + l * HH * VV,
            Wg  + l * DD * VV,
            bg  + l * VV);
        update_kernel<<<(upd_threads + 255) / 256, 256>>>(
            (l == NLAYER - 1) ? (float*)d_out : nullptr);
    }
}

// round 4
// speedup vs baseline: 1.3267x; 1.3218x over previous
#include <cuda_runtime.h>
#include <cuda_bf16.h>

#define S_IN   44
#define HID    128
#define DD     64
#define VV     16
#define HH     16
#define NRBF   16
#define NEF    16
#define VCIN   17
#define NN     50000
#define NE     800000
#define NLAYER 3

__device__ float g_s[NN * DD];
__device__ float g_v[NN * VV * 3];
__device__ float g_P[NN * DD];        // per-layer node hoist: s@Ws[0:64]+bs
__device__ float g_aggs[NN * DD];
__device__ float g_aggv[NN * 64];     // padded [node][o:16][4]
__device__ float g_deg[NN];
__device__ float g_invdeg[NN];

__device__ __forceinline__ void red_add_v4(float* p, float a, float b, float c, float d)
{
    asm volatile("red.global.add.v4.f32 [%0], {%1,%2,%3,%4};"
                 :: "l"(p), "f"(a), "f"(b), "f"(c), "f"(d) : "memory");
}

// ---------------- node embedding (unchanged, known correct) ----------------
__global__ __launch_bounds__(128) void embed_kernel(
    const float* __restrict__ sf, const float* __restrict__ W1,
    const float* __restrict__ b1, const float* __restrict__ W2,
    const float* __restrict__ b2, const float* __restrict__ vf)
{
    __shared__ float ssf[8][S_IN];
    __shared__ float sh[8][HID];
    const int nb = blockIdx.x * 8;
    const int t  = threadIdx.x;

    for (int i = t; i < 8 * S_IN; i += 128) {
        int n = i / S_IN, k = i - n * S_IN;
        int node = nb + n;
        ssf[n][k] = (node < NN) ? sf[node * S_IN + k] : 0.f;
    }
    __syncthreads();

    float acc[8];
    float bb = b1[t];
#pragma unroll
    for (int n = 0; n < 8; n++) acc[n] = bb;
    for (int k = 0; k < S_IN; k++) {
        float w = W1[k * HID + t];
#pragma unroll
        for (int n = 0; n < 8; n++) acc[n] += ssf[n][k] * w;
    }
#pragma unroll
    for (int n = 0; n < 8; n++) sh[n][t] = fmaxf(acc[n], 0.f);
    __syncthreads();

    if (t < DD) {
        float acc2[8];
        float b2v = b2[t];
#pragma unroll
        for (int n = 0; n < 8; n++) acc2[n] = b2v;
        for (int k = 0; k < HID; k++) {
            float w = W2[k * DD + t];
#pragma unroll
            for (int n = 0; n < 8; n++) acc2[n] += sh[n][k] * w;
        }
#pragma unroll
        for (int n = 0; n < 8; n++)
            if (nb + n < NN) g_s[(nb + n) * DD + t] = acc2[n];
    }
    for (int i = t; i < 8 * VV * 3; i += 128) {
        int n = i / (VV * 3), k = i - n * (VV * 3);
        int node = nb + n;
        if (node < NN) g_v[node * VV * 3 + k] = vf[node * VV * 3 + k];
    }
}

__global__ void deg_kernel(const int* __restrict__ ei)
{
    int e = blockIdx.x * blockDim.x + threadIdx.x;
    if (e < NE) atomicAdd(&g_deg[ei[NE + e]], 1.0f);
}
__global__ void invdeg_kernel()
{
    int i = blockIdx.x * blockDim.x + threadIdx.x;
    if (i < NN) g_invdeg[i] = 1.0f / fmaxf(g_deg[i], 1.0f);
}

// ---------------- per-layer hoist: P = s @ Ws[0:64] + bs ----------------
// block: 32 nodes, 256 threads (8 threads/node, 8 cols each)
__global__ __launch_bounds__(256) void pre_kernel(
    const float* __restrict__ WsP, const float* __restrict__ bs)
{
    __shared__ float sW[64 * 64];
    __shared__ float sS[32 * 65];
    const int t = threadIdx.x;
    const int nb = blockIdx.x * 32;

    for (int i = t; i < 64 * 64; i += 256) sW[i] = WsP[i];
    for (int i = t; i < 32 * 64; i += 256) {
        int n = i >> 6, k = i & 63;
        sS[n * 65 + k] = (nb + n < NN) ? g_s[(size_t)(nb + n) * 64 + k] : 0.f;
    }
    __syncthreads();

    const int nl = t >> 3, j0 = (t & 7) * 8;
    float4 a0 = *(const float4*)(bs + j0);
    float4 a1 = *(const float4*)(bs + j0 + 4);
#pragma unroll 8
    for (int k = 0; k < 64; k++) {
        float a = sS[nl * 65 + k];
        float4 w0 = *(const float4*)&sW[k * 64 + j0];
        float4 w1 = *(const float4*)&sW[k * 64 + j0 + 4];
        a0.x += a * w0.x; a0.y += a * w0.y; a0.z += a * w0.z; a0.w += a * w0.w;
        a1.x += a * w1.x; a1.y += a * w1.y; a1.z += a * w1.z; a1.w += a * w1.w;
    }
    const int node = nb + nl;
    if (node < NN) {
        *(float4*)&g_P[(size_t)node * 64 + j0]     = a0;
        *(float4*)&g_P[(size_t)node * 64 + j0 + 4] = a1;
    }
}

// ---------------- edge kernel: warp = 4 edges, 48-wide GEMV ----------------
// scratch/edge (160 floats): X[0:48]=rbf|ef|vnorm, Vh[48:96], U[96:160]=vin->SM
#define EPW 4
#define SCR 160
#define NWARP 8
#define OFF_WSV 0
#define OFF_WH  (OFF_WSV + 48 * 64)        // 3072
#define OFF_WMU (OFF_WH  + VCIN * HH)      // +272
#define OFF_WG  (OFF_WMU + HH * VV)        // +256
#define OFF_BG  (OFF_WG  + DD * VV)        // +1024
#define OFF_SCR (OFF_BG  + VV)             // +16
#define SMEM_FLOATS (OFF_SCR + NWARP * EPW * SCR)
#define SMEM_BYTES  (SMEM_FLOATS * 4)

__global__ __launch_bounds__(256) void edge_kernel(
    const float* __restrict__ ef, const float* __restrict__ xd,
    const float* __restrict__ dvec, const int* __restrict__ ei,
    const float* __restrict__ Wh, const float* __restrict__ WsV,
    const float* __restrict__ Wmu, const float* __restrict__ Wg,
    const float* __restrict__ bg)
{
    extern __shared__ float smem[];
    float* sWsV = smem + OFF_WSV;
    float* sWh  = smem + OFF_WH;
    float* sWmu = smem + OFF_WMU;
    float* sWg  = smem + OFF_WG;
    float* sbg  = smem + OFF_BG;

    const int t = threadIdx.x;
    for (int i = t; i < 48 * 64; i += 256) sWsV[i] = WsV[i];
    for (int i = t; i < VCIN * HH; i += 256) sWh[i] = Wh[i];
    if (t < HH * VV) sWmu[t] = Wmu[t];
    for (int i = t; i < DD * VV; i += 256) sWg[i] = Wg[i];
    if (t < VV) sbg[t] = bg[t];
    __syncthreads();

    const int warp = t >> 5, lane = t & 31;
    float* scr = smem + OFF_SCR + warp * EPW * SCR;

    const float inv_sigma = (float)NRBF / 10.0f;
    const float mu_step   = 10.0f / (float)(NRBF - 1);

    const int ntiles = NE / (NWARP * EPW);   // exact: 25000
    for (int tile = blockIdx.x; tile < ntiles; tile += gridDim.x) {
        const int ebase = tile * (NWARP * EPW) + warp * EPW;
        int srcs[EPW], dsts[EPW];

        // Phase 1: rbf | ef | vin
#pragma unroll
        for (int q = 0; q < EPW; q++) {
            const int e = ebase + q;
            float* X = scr + q * SCR;
            float* U = X + 96;
            srcs[q] = ei[e];
            dsts[q] = ei[NE + e];
            if (lane < 16) {
                float de = dvec[e];
                float tt = (de - (float)lane * mu_step) * inv_sigma;
                X[lane]      = __expf(-tt * tt);
                X[16 + lane] = ef[e * NEF + lane];
            }
            U[lane] = g_v[srcs[q] * 48 + lane];
            if (lane < 19) {
                int idx = 32 + lane;
                U[idx] = (idx < 48) ? g_v[srcs[q] * 48 + idx] : xd[e * 3 + (idx - 48)];
            }
        }
        __syncwarp();

        // Phase 2: Vh + vnorm
#pragma unroll
        for (int q = 0; q < EPW; q++) {
            float* X = scr + q * SCR;
            float* Vh = X + 48;
            float* vin = X + 96;
            {
                int i = lane, h = i / 3, d = i - h * 3;
                float a = 0.f;
#pragma unroll
                for (int c = 0; c < VCIN; c++) a += vin[c * 3 + d] * sWh[c * HH + h];
                Vh[i] = a;
            }
            if (lane < 16) {
                int i = lane + 32, h = i / 3, d = i - h * 3;
                float a = 0.f;
#pragma unroll
                for (int c = 0; c < VCIN; c++) a += vin[c * 3 + d] * sWh[c * HH + h];
                Vh[i] = a;
            }
        }
        __syncwarp();
#pragma unroll
        for (int q = 0; q < EPW; q++) {
            float* X = scr + q * SCR;
            if (lane < 16) {
                float a = X[48 + lane * 3], b = X[49 + lane * 3], c = X[50 + lane * 3];
                X[32 + lane] = sqrtf(a * a + b * b + c * c + 1e-8f);
            }
        }
        __syncwarp();

        // Phase 3: sm = relu(P[src] + X @ WsV), 4 edges jointly
        const int j0 = 2 * lane;
        float acc[EPW][2];
#pragma unroll
        for (int q = 0; q < EPW; q++) {
            float2 p = *(const float2*)&g_P[(size_t)srcs[q] * 64 + j0];
            acc[q][0] = p.x; acc[q][1] = p.y;
        }
        {
            const float* X0 = scr;
            const float* X1 = scr + SCR;
            const float* X2 = scr + 2 * SCR;
            const float* X3 = scr + 3 * SCR;
#pragma unroll
            for (int k = 0; k < 48; k += 4) {
                float4 x0 = *(const float4*)(X0 + k);
                float4 x1 = *(const float4*)(X1 + k);
                float4 x2 = *(const float4*)(X2 + k);
                float4 x3 = *(const float4*)(X3 + k);
#pragma unroll
                for (int kk = 0; kk < 4; kk++) {
                    float2 w = *(const float2*)&sWsV[(k + kk) * DD + j0];
                    float a0 = ((const float*)&x0)[kk];
                    float a1 = ((const float*)&x1)[kk];
                    float a2 = ((const float*)&x2)[kk];
                    float a3 = ((const float*)&x3)[kk];
                    acc[0][0] += a0 * w.x; acc[0][1] += a0 * w.y;
                    acc[1][0] += a1 * w.x; acc[1][1] += a1 * w.y;
                    acc[2][0] += a2 * w.x; acc[2][1] += a2 * w.y;
                    acc[3][0] += a3 * w.x; acc[3][1] += a3 * w.y;
                }
            }
        }
#pragma unroll
        for (int q = 0; q < EPW; q++) {
            float* SM = scr + q * SCR + 96;
            SM[j0]     = fmaxf(acc[q][0], 0.f);
            SM[j0 + 1] = fmaxf(acc[q][1], 0.f);
        }
        __syncwarp();

        // scatter sm (v4 reductions) — lanes 0..15
#pragma unroll
        for (int q = 0; q < EPW; q++) {
            if (lane < 16) {
                float* SM = scr + q * SCR + 96;
                float4 v = *(const float4*)&SM[lane * 4];
                red_add_v4(&g_aggs[(size_t)dsts[q] * 64 + lane * 4], v.x, v.y, v.z, v.w);
            }
        }

        // Phase 4: gate into X[0:16]
#pragma unroll
        for (int q = 0; q < EPW; q++) {
            float* X = scr + q * SCR;
            float* SM = X + 96;
            if (lane < VV) {
                float a = sbg[lane];
#pragma unroll 8
                for (int j = 0; j < DD; j++) a += SM[j] * sWg[j * VV + lane];
                X[lane] = 1.f / (1.f + __expf(-a));
            }
        }
        __syncwarp();

        // Phase 5: vm = (Vh @ Wmu) * gate, v4 scatter — lane = o
#pragma unroll
        for (int q = 0; q < EPW; q++) {
            float* X = scr + q * SCR;
            float* Vh = X + 48;
            if (lane < 16) {
                float vx = 0.f, vy = 0.f, vz = 0.f;
#pragma unroll
                for (int h = 0; h < HH; h++) {
                    float w = sWmu[h * VV + lane];
                    vx += Vh[h * 3]     * w;
                    vy += Vh[h * 3 + 1] * w;
                    vz += Vh[h * 3 + 2] * w;
                }
                float g = X[lane];
                red_add_v4(&g_aggv[(size_t)dsts[q] * 64 + lane * 4],
                           vx * g, vy * g, vz * g, 0.f);
            }
        }
        __syncwarp();
    }
}

// ---------------- update ----------------
__global__ void update_kernel(float* __restrict__ out)
{
    int i = blockIdx.x * blockDim.x + threadIdx.x;
    if (i < NN * DD) {
        float val = g_s[i] + g_aggs[i] * g_invdeg[i >> 6];
        g_s[i] = val;
        if (out) out[i] = val;
    } else {
        int j = i - NN * DD;
        if (j < NN * 48) {
            int node = j / 48, r = j - node * 48;
            int o = r / 3, d = r - o * 3;
            g_v[j] += g_aggv[node * 64 + o * 4 + d] * g_invdeg[node];
        }
    }
}

extern "C" void kernel_launch(void* const* d_in, const int* in_sizes, int n_in,
                              void* d_out, int out_size)
{
    const float* sf  = (const float*)d_in[0];
    const float* vf  = (const float*)d_in[2];
    const float* ef  = (const float*)d_in[3];
    const float* xd  = (const float*)d_in[4];
    const float* dv  = (const float*)d_in[5];
    const int*   eix = (const int*)  d_in[6];
    const float* W1  = (const float*)d_in[7];
    const float* b1  = (const float*)d_in[8];
    const float* W2  = (const float*)d_in[9];
    const float* b2  = (const float*)d_in[10];
    const float* Wh  = (const float*)d_in[11];
    const float* Ws  = (const float*)d_in[12];
    const float* bs  = (const float*)d_in[13];
    const float* Wmu = (const float*)d_in[14];
    const float* Wg  = (const float*)d_in[15];
    const float* bg  = (const float*)d_in[16];
    (void)in_sizes; (void)n_in; (void)out_size;

    cudaFuncSetAttribute(edge_kernel,
                         cudaFuncAttributeMaxDynamicSharedMemorySize, SMEM_BYTES);

    void *p_deg = nullptr, *p_aggs = nullptr, *p_aggv = nullptr;
    cudaGetSymbolAddress(&p_deg,  g_deg);
    cudaGetSymbolAddress(&p_aggs, g_aggs);
    cudaGetSymbolAddress(&p_aggv, g_aggv);

    embed_kernel<<<(NN + 7) / 8, 128>>>(sf, W1, b1, W2, b2, vf);
    cudaMemsetAsync(p_deg, 0, NN * sizeof(float));
    deg_kernel<<<(NE + 255) / 256, 256>>>(eix);
    invdeg_kernel<<<(NN + 255) / 256, 256>>>();

    const int upd_threads = NN * DD + NN * 48;
    for (int l = 0; l < NLAYER; l++) {
        pre_kernel<<<(NN + 31) / 32, 256>>>(Ws + (size_t)l * 112 * 64, bs + l * DD);
        cudaMemsetAsync(p_aggs, 0, (size_t)NN * 64 * sizeof(float));
        cudaMemsetAsync(p_aggv, 0, (size_t)NN * 64 * sizeof(float));
        edge_kernel<<<592, 256, SMEM_BYTES>>>(
            ef, xd, dv, eix,
            Wh  + l * VCIN * HH,
            Ws  + (size_t)l * 112 * 64 + 64 * 64,
            Wmu + l * HH * VV,
            Wg  + l * DD * VV,
            bg  + l * VV);
        update_kernel<<<(upd_threads + 255) / 256, 256>>>(
            (l == NLAYER - 1) ? (float*)d_out : nullptr);
    }
}

// round 5
// speedup vs baseline: 1.5699x; 1.1833x over previous
#include <cuda_runtime.h>
#include <cuda_bf16.h>

#define S_IN   44
#define HID    128
#define DD     64
#define VV     16
#define HH     16
#define NRBF   16
#define NEF    16
#define VCIN   17
#define NN     50000
#define NE     800000
#define NLAYER 3

__device__ float g_s[NN * DD];
__device__ float g_v[NN * VV * 3];
__device__ float g_P[NN * DD];        // per-layer node hoist: s@Ws[0:64]+bs
__device__ float g_aggs[NN * DD];
__device__ float g_aggv[NN * 64];     // padded [node][o:16][4]
__device__ float g_deg[NN];
__device__ float g_invdeg[NN];

__device__ __forceinline__ void red_add_v4(float* p, float a, float b, float c, float d)
{
    asm volatile("red.global.add.v4.f32 [%0], {%1,%2,%3,%4};"
                 :: "l"(p), "f"(a), "f"(b), "f"(c), "f"(d) : "memory");
}

// ---------------- node embedding ----------------
__global__ __launch_bounds__(128) void embed_kernel(
    const float* __restrict__ sf, const float* __restrict__ W1,
    const float* __restrict__ b1, const float* __restrict__ W2,
    const float* __restrict__ b2, const float* __restrict__ vf)
{
    __shared__ float ssf[8][S_IN];
    __shared__ float sh[8][HID];
    const int nb = blockIdx.x * 8;
    const int t  = threadIdx.x;

    for (int i = t; i < 8 * S_IN; i += 128) {
        int n = i / S_IN, k = i - n * S_IN;
        int node = nb + n;
        ssf[n][k] = (node < NN) ? sf[node * S_IN + k] : 0.f;
    }
    __syncthreads();

    float acc[8];
    float bb = b1[t];
#pragma unroll
    for (int n = 0; n < 8; n++) acc[n] = bb;
    for (int k = 0; k < S_IN; k++) {
        float w = W1[k * HID + t];
#pragma unroll
        for (int n = 0; n < 8; n++) acc[n] += ssf[n][k] * w;
    }
#pragma unroll
    for (int n = 0; n < 8; n++) sh[n][t] = fmaxf(acc[n], 0.f);
    __syncthreads();

    if (t < DD) {
        float acc2[8];
        float b2v = b2[t];
#pragma unroll
        for (int n = 0; n < 8; n++) acc2[n] = b2v;
        for (int k = 0; k < HID; k++) {
            float w = W2[k * DD + t];
#pragma unroll
            for (int n = 0; n < 8; n++) acc2[n] += sh[n][k] * w;
        }
#pragma unroll
        for (int n = 0; n < 8; n++)
            if (nb + n < NN) g_s[(nb + n) * DD + t] = acc2[n];
    }
    for (int i = t; i < 8 * VV * 3; i += 128) {
        int n = i / (VV * 3), k = i - n * (VV * 3);
        int node = nb + n;
        if (node < NN) g_v[node * VV * 3 + k] = vf[node * VV * 3 + k];
    }
}

__global__ void deg_kernel(const int* __restrict__ ei)
{
    int e = blockIdx.x * blockDim.x + threadIdx.x;
    if (e < NE) atomicAdd(&g_deg[ei[NE + e]], 1.0f);
}
__global__ void invdeg_kernel()
{
    int i = blockIdx.x * blockDim.x + threadIdx.x;
    if (i < NN) g_invdeg[i] = 1.0f / fmaxf(g_deg[i], 1.0f);
}

// ---------------- per-layer hoist: P = s @ Ws[0:64] + bs ----------------
__global__ __launch_bounds__(256) void pre_kernel(
    const float* __restrict__ WsP, const float* __restrict__ bs)
{
    __shared__ float sW[64 * 64];
    __shared__ float sS[32 * 65];
    const int t = threadIdx.x;
    const int nb = blockIdx.x * 32;

    for (int i = t; i < 64 * 64; i += 256) sW[i] = WsP[i];
    for (int i = t; i < 32 * 64; i += 256) {
        int n = i >> 6, k = i & 63;
        sS[n * 65 + k] = (nb + n < NN) ? g_s[(size_t)(nb + n) * 64 + k] : 0.f;
    }
    __syncthreads();

    const int nl = t >> 3, j0 = (t & 7) * 8;
    float4 a0 = *(const float4*)(bs + j0);
    float4 a1 = *(const float4*)(bs + j0 + 4);
#pragma unroll 8
    for (int k = 0; k < 64; k++) {
        float a = sS[nl * 65 + k];
        float4 w0 = *(const float4*)&sW[k * 64 + j0];
        float4 w1 = *(const float4*)&sW[k * 64 + j0 + 4];
        a0.x += a * w0.x; a0.y += a * w0.y; a0.z += a * w0.z; a0.w += a * w0.w;
        a1.x += a * w1.x; a1.y += a * w1.y; a1.z += a * w1.z; a1.w += a * w1.w;
    }
    const int node = nb + nl;
    if (node < NN) {
        *(float4*)&g_P[(size_t)node * 64 + j0]     = a0;
        *(float4*)&g_P[(size_t)node * 64 + j0 + 4] = a1;
    }
}

// ---------------- edge kernel: warp = 4 edges ----------------
// per-edge scratch (176 floats):
//  [0:16]  rbf -> gate      [16:32] ef       [32:48] vnorm
//  [48:96] Vh               [96:160] vin(51) -> SM(64) -> VM(64 padded)
#define EPW 4
#define SCR 176
#define NWARP 8
#define OFF_WSV 0
#define OFF_WH  (48 * 64)                  // 3072
#define OFF_WMU (OFF_WH + VCIN * HH)       // 3344
#define OFF_WG  (OFF_WMU + HH * VV)        // 3600
#define OFF_BG  (OFF_WG + DD * VV)         // 4624
#define OFF_SCR (OFF_BG + VV)              // 4640
#define SMEM_FLOATS (OFF_SCR + NWARP * EPW * SCR)
#define SMEM_BYTES  (SMEM_FLOATS * 4)

__global__ __launch_bounds__(256) void edge_kernel(
    const float* __restrict__ ef, const float* __restrict__ xd,
    const float* __restrict__ dvec, const int* __restrict__ ei,
    const float* __restrict__ Wh, const float* __restrict__ WsV,
    const float* __restrict__ Wmu, const float* __restrict__ Wg,
    const float* __restrict__ bg)
{
    extern __shared__ float smem[];
    float* sWsV = smem + OFF_WSV;
    float* sWh  = smem + OFF_WH;
    float* sWmu = smem + OFF_WMU;
    float* sWg  = smem + OFF_WG;
    float* sbg  = smem + OFF_BG;

    const int t = threadIdx.x;
    for (int i = t; i < 48 * 64; i += 256) sWsV[i] = WsV[i];
    for (int i = t; i < VCIN * HH; i += 256) sWh[i] = Wh[i];
    if (t < HH * VV) sWmu[t] = Wmu[t];
    for (int i = t; i < DD * VV; i += 256) sWg[i] = Wg[i];
    if (t < VV) sbg[t] = bg[t];
    __syncthreads();

    const int warp = t >> 5, lane = t & 31;
    float* scr = smem + OFF_SCR + warp * EPW * SCR;

    // precomputed role indices
    const int h0 = lane / 3, d0 = lane - 3 * h0;            // pass0: i = lane
    const int i1 = 32 + lane;
    int h1 = i1 / 3; const int d1 = i1 - 3 * h1;            // pass1: i = 32+lane
    if (h1 > 15) h1 = 15;                                   // clamp (lanes>=16 unused)
    const int q4 = lane >> 3, o0g = (lane & 7) * 2;         // gate roles

    const float inv_sigma = (float)NRBF / 10.0f;
    const float mu_step   = 10.0f / (float)(NRBF - 1);

    const int ntiles = NE / (NWARP * EPW);   // 25000 exact
    for (int tile = blockIdx.x; tile < ntiles; tile += gridDim.x) {
        const int ebase = tile * (NWARP * EPW) + warp * EPW;
        int srcs[EPW], dsts[EPW];

        // ---- Phase 1: rbf | ef | vin ----
#pragma unroll
        for (int q = 0; q < EPW; q++) {
            const int e = ebase + q;
            float* X = scr + q * SCR;
            float* U = X + 96;
            srcs[q] = ei[e];
            dsts[q] = ei[NE + e];
            if (lane < 16) {
                float de = dvec[e];
                float tt = (de - (float)lane * mu_step) * inv_sigma;
                X[lane]      = __expf(-tt * tt);
                X[16 + lane] = ef[e * NEF + lane];
            }
            U[lane] = g_v[srcs[q] * 48 + lane];
            if (lane < 19) {
                int idx = 32 + lane;
                U[idx] = (idx < 48) ? g_v[srcs[q] * 48 + idx] : xd[e * 3 + (idx - 48)];
            }
        }
        __syncwarp();

        // ---- Phase 2: Vh = vin @ Wh (weights loaded once per c, 4 edges inner) ----
        {
            float a0[EPW] = {0.f, 0.f, 0.f, 0.f};
            float a1[EPW] = {0.f, 0.f, 0.f, 0.f};
#pragma unroll
            for (int c = 0; c < VCIN; c++) {
                float w0 = sWh[c * HH + h0];
                float w1 = sWh[c * HH + h1];
#pragma unroll
                for (int q = 0; q < EPW; q++) {
                    const float* U = scr + q * SCR + 96;
                    a0[q] += U[c * 3 + d0] * w0;
                    a1[q] += U[c * 3 + d1] * w1;
                }
            }
#pragma unroll
            for (int q = 0; q < EPW; q++) {
                float* Vh = scr + q * SCR + 48;
                Vh[lane] = a0[q];
                if (lane < 16) Vh[32 + lane] = a1[q];
            }
        }
        __syncwarp();

        // ---- vnorm into X[32:48] ----
        if (lane < 16) {
#pragma unroll
            for (int q = 0; q < EPW; q++) {
                float* X = scr + q * SCR;
                float a = X[48 + 3 * lane], b = X[49 + 3 * lane], c = X[50 + 3 * lane];
                X[32 + lane] = sqrtf(a * a + b * b + c * c + 1e-8f);
            }
        }
        __syncwarp();

        // ---- Phase 3: sm = relu(P[src] + X @ WsV) ----
        const int j0 = 2 * lane;
        float acc[EPW][2];
#pragma unroll
        for (int q = 0; q < EPW; q++) {
            float2 p = *(const float2*)&g_P[(size_t)srcs[q] * 64 + j0];
            acc[q][0] = p.x; acc[q][1] = p.y;
        }
        {
            const float* X0 = scr;
            const float* X1 = scr + SCR;
            const float* X2 = scr + 2 * SCR;
            const float* X3 = scr + 3 * SCR;
#pragma unroll
            for (int k = 0; k < 48; k += 4) {
                float4 x0 = *(const float4*)(X0 + k);
                float4 x1 = *(const float4*)(X1 + k);
                float4 x2 = *(const float4*)(X2 + k);
                float4 x3 = *(const float4*)(X3 + k);
#pragma unroll
                for (int kk = 0; kk < 4; kk++) {
                    float2 w = *(const float2*)&sWsV[(k + kk) * DD + j0];
                    float a0 = ((const float*)&x0)[kk];
                    float a1 = ((const float*)&x1)[kk];
                    float a2 = ((const float*)&x2)[kk];
                    float a3 = ((const float*)&x3)[kk];
                    acc[0][0] += a0 * w.x; acc[0][1] += a0 * w.y;
                    acc[1][0] += a1 * w.x; acc[1][1] += a1 * w.y;
                    acc[2][0] += a2 * w.x; acc[2][1] += a2 * w.y;
                    acc[3][0] += a3 * w.x; acc[3][1] += a3 * w.y;
                }
            }
        }
#pragma unroll
        for (int q = 0; q < EPW; q++) {
            float* SM = scr + q * SCR + 96;
            SM[j0]     = fmaxf(acc[q][0], 0.f);
            SM[j0 + 1] = fmaxf(acc[q][1], 0.f);
        }
        __syncwarp();

        // ---- scatter sm (v4) ----
#pragma unroll
        for (int q = 0; q < EPW; q++) {
            if (lane < 16) {
                const float* SM = scr + q * SCR + 96;
                float4 v = *(const float4*)&SM[lane * 4];
                red_add_v4(&g_aggs[(size_t)dsts[q] * 64 + lane * 4], v.x, v.y, v.z, v.w);
            }
        }

        // ---- Phase 4: gate (all 32 lanes: lane -> (edge q4, cols o0g,o0g+1)) ----
        {
            const float* SM = scr + q4 * SCR + 96;
            float a = sbg[o0g], b = sbg[o0g + 1];
#pragma unroll 8
            for (int j = 0; j < DD; j++) {
                float s = SM[j];
                float2 w = *(const float2*)&sWg[j * VV + o0g];
                a += s * w.x; b += s * w.y;
            }
            float* X = scr + q4 * SCR;
            X[o0g]     = 1.f / (1.f + __expf(-a));
            X[o0g + 1] = 1.f / (1.f + __expf(-b));
        }
        __syncwarp();

        // ---- Phase 5: vm = (Vh @ Wmu) * gate -> padded VM[o][4] ----
        {
            float b0[EPW] = {0.f, 0.f, 0.f, 0.f};
            float b1[EPW] = {0.f, 0.f, 0.f, 0.f};
#pragma unroll
            for (int h = 0; h < HH; h++) {
                float w0 = sWmu[h * VV + h0];   // h0 = lane/3 doubles as o for pass0
                float w1 = sWmu[h * VV + h1];
#pragma unroll
                for (int q = 0; q < EPW; q++) {
                    const float* Vh = scr + q * SCR + 48;
                    b0[q] += Vh[h * 3 + d0] * w0;
                    b1[q] += Vh[h * 3 + d1] * w1;
                }
            }
#pragma unroll
            for (int q = 0; q < EPW; q++) {
                float* X  = scr + q * SCR;
                float* VM = X + 96;            // SM dead after phase 4
                VM[h0 * 4 + d0] = b0[q] * X[h0];
                if (lane < 16) VM[h1 * 4 + d1] = b1[q] * X[h1];
                else           VM[(lane - 16) * 4 + 3] = 0.f;
            }
        }
        __syncwarp();

        // ---- scatter vm (v4) ----
#pragma unroll
        for (int q = 0; q < EPW; q++) {
            if (lane < 16) {
                const float* VM = scr + q * SCR + 96;
                float4 v = *(const float4*)&VM[lane * 4];
                red_add_v4(&g_aggv[(size_t)dsts[q] * 64 + lane * 4], v.x, v.y, v.z, v.w);
            }
        }
        __syncwarp();
    }
}

// ---------------- update ----------------
__global__ void update_kernel(float* __restrict__ out)
{
    int i = blockIdx.x * blockDim.x + threadIdx.x;
    if (i < NN * DD) {
        float val = g_s[i] + g_aggs[i] * g_invdeg[i >> 6];
        g_s[i] = val;
        if (out) out[i] = val;
    } else {
        int j = i - NN * DD;
        if (j < NN * 48) {
            int node = j / 48, r = j - node * 48;
            int o = r / 3, d = r - o * 3;
            g_v[j] += g_aggv[node * 64 + o * 4 + d] * g_invdeg[node];
        }
    }
}

extern "C" void kernel_launch(void* const* d_in, const int* in_sizes, int n_in,
                              void* d_out, int out_size)
{
    const float* sf  = (const float*)d_in[0];
    const float* vf  = (const float*)d_in[2];
    const float* ef  = (const float*)d_in[3];
    const float* xd  = (const float*)d_in[4];
    const float* dv  = (const float*)d_in[5];
    const int*   eix = (const int*)  d_in[6];
    const float* W1  = (const float*)d_in[7];
    const float* b1  = (const float*)d_in[8];
    const float* W2  = (const float*)d_in[9];
    const float* b2  = (const float*)d_in[10];
    const float* Wh  = (const float*)d_in[11];
    const float* Ws  = (const float*)d_in[12];
    const float* bs  = (const float*)d_in[13];
    const float* Wmu = (const float*)d_in[14];
    const float* Wg  = (const float*)d_in[15];
    const float* bg  = (const float*)d_in[16];
    (void)in_sizes; (void)n_in; (void)out_size;

    cudaFuncSetAttribute(edge_kernel,
                         cudaFuncAttributeMaxDynamicSharedMemorySize, SMEM_BYTES);

    void *p_deg = nullptr, *p_aggs = nullptr, *p_aggv = nullptr;
    cudaGetSymbolAddress(&p_deg,  g_deg);
    cudaGetSymbolAddress(&p_aggs, g_aggs);
    cudaGetSymbolAddress(&p_aggv, g_aggv);

    embed_kernel<<<(NN + 7) / 8, 128>>>(sf, W1, b1, W2, b2, vf);
    cudaMemsetAsync(p_deg, 0, NN * sizeof(float));
    deg_kernel<<<(NE + 255) / 256, 256>>>(eix);
    invdeg_kernel<<<(NN + 255) / 256, 256>>>();

    const int upd_threads = NN * DD + NN * 48;
    for (int l = 0; l < NLAYER; l++) {
        pre_kernel<<<(NN + 31) / 32, 256>>>(Ws + (size_t)l * 112 * 64, bs + l * DD);
        cudaMemsetAsync(p_aggs, 0, (size_t)NN * 64 * sizeof(float));
        cudaMemsetAsync(p_aggv, 0, (size_t)NN * 64 * sizeof(float));
        edge_kernel<<<740, 256, SMEM_BYTES>>>(
            ef, xd, dv, eix,
            Wh  + l * VCIN * HH,
            Ws  + (size_t)l * 112 * 64 + 64 * 64,
            Wmu + l * HH * VV,
            Wg  + l * DD * VV,
            bg  + l * VV);
        update_kernel<<<(upd_threads + 255) / 256, 256>>>(
            (l == NLAYER - 1) ? (float*)d_out : nullptr);
    }
}

// round 6
// speedup vs baseline: 1.6283x; 1.0372x over previous
#include <cuda_runtime.h>
#include <cuda_bf16.h>

#define S_IN   44
#define HID    128
#define DD     64
#define VV     16
#define HH     16
#define NRBF   16
#define NEF    16
#define VCIN   17
#define NN     50000
#define NE     800000
#define NLAYER 3

__device__ float g_s[NN * DD];
__device__ float g_v[NN * VV * 3];
__device__ float g_P[NN * DD];
__device__ float g_aggs[NN * DD];
__device__ float g_aggv[NN * 64];     // padded [node][o:16][4]
__device__ float g_deg[NN];
__device__ float g_invdeg[NN];

__device__ __forceinline__ void red_add_v4(float* p, float a, float b, float c, float d)
{
    asm volatile("red.global.add.v4.f32 [%0], {%1,%2,%3,%4};"
                 :: "l"(p), "f"(a), "f"(b), "f"(c), "f"(d) : "memory");
}

// ---------------- node embedding ----------------
__global__ __launch_bounds__(128) void embed_kernel(
    const float* __restrict__ sf, const float* __restrict__ W1,
    const float* __restrict__ b1, const float* __restrict__ W2,
    const float* __restrict__ b2, const float* __restrict__ vf)
{
    __shared__ float ssf[8][S_IN];
    __shared__ float sh[8][HID];
    const int nb = blockIdx.x * 8;
    const int t  = threadIdx.x;

    for (int i = t; i < 8 * S_IN; i += 128) {
        int n = i / S_IN, k = i - n * S_IN;
        int node = nb + n;
        ssf[n][k] = (node < NN) ? sf[node * S_IN + k] : 0.f;
    }
    __syncthreads();

    float acc[8];
    float bb = b1[t];
#pragma unroll
    for (int n = 0; n < 8; n++) acc[n] = bb;
    for (int k = 0; k < S_IN; k++) {
        float w = W1[k * HID + t];
#pragma unroll
        for (int n = 0; n < 8; n++) acc[n] += ssf[n][k] * w;
    }
#pragma unroll
    for (int n = 0; n < 8; n++) sh[n][t] = fmaxf(acc[n], 0.f);
    __syncthreads();

    if (t < DD) {
        float acc2[8];
        float b2v = b2[t];
#pragma unroll
        for (int n = 0; n < 8; n++) acc2[n] = b2v;
        for (int k = 0; k < HID; k++) {
            float w = W2[k * DD + t];
#pragma unroll
            for (int n = 0; n < 8; n++) acc2[n] += sh[n][k] * w;
        }
#pragma unroll
        for (int n = 0; n < 8; n++)
            if (nb + n < NN) g_s[(nb + n) * DD + t] = acc2[n];
    }
    for (int i = t; i < 8 * VV * 3; i += 128) {
        int n = i / (VV * 3), k = i - n * (VV * 3);
        int node = nb + n;
        if (node < NN) g_v[node * VV * 3 + k] = vf[node * VV * 3 + k];
    }
}

__global__ void deg_kernel(const int* __restrict__ ei)
{
    int e = blockIdx.x * blockDim.x + threadIdx.x;
    if (e < NE) atomicAdd(&g_deg[ei[NE + e]], 1.0f);
}
__global__ void invdeg_kernel()
{
    int i = blockIdx.x * blockDim.x + threadIdx.x;
    if (i < NN) g_invdeg[i] = 1.0f / fmaxf(g_deg[i], 1.0f);
}

// ---------------- layer-0 hoist: P = s @ Ws[0:64] + bs ----------------
__global__ __launch_bounds__(256) void pre_kernel(
    const float* __restrict__ WsP, const float* __restrict__ bs)
{
    __shared__ float sW[64 * 64];
    __shared__ float sS[32 * 65];
    const int t = threadIdx.x;
    const int nb = blockIdx.x * 32;

    for (int i = t; i < 64 * 64; i += 256) sW[i] = WsP[i];
    for (int i = t; i < 32 * 64; i += 256) {
        int n = i >> 6, k = i & 63;
        sS[n * 65 + k] = (nb + n < NN) ? g_s[(size_t)(nb + n) * 64 + k] : 0.f;
    }
    __syncthreads();

    const int nl = t >> 3, j0 = (t & 7) * 8;
    float4 a0 = *(const float4*)(bs + j0);
    float4 a1 = *(const float4*)(bs + j0 + 4);
#pragma unroll 8
    for (int k = 0; k < 64; k++) {
        float a = sS[nl * 65 + k];
        float4 w0 = *(const float4*)&sW[k * 64 + j0];
        float4 w1 = *(const float4*)&sW[k * 64 + j0 + 4];
        a0.x += a * w0.x; a0.y += a * w0.y; a0.z += a * w0.z; a0.w += a * w0.w;
        a1.x += a * w1.x; a1.y += a * w1.y; a1.z += a * w1.z; a1.w += a * w1.w;
    }
    const int node = nb + nl;
    if (node < NN) {
        *(float4*)&g_P[(size_t)node * 64 + j0]     = a0;
        *(float4*)&g_P[(size_t)node * 64 + j0 + 4] = a1;
    }
}

// ---------------- edge kernel ----------------
// per-edge scratch (SCR=180 floats, stripes conflict-free mod 32):
//  [0:16]  rbf -> gate   [16:32] ef   [32:48] vnorm
//  [48:96] Vh            [96:160] vin(51) -> SM(64)
#define EPW 4
#define SCR 180
#define NWARP 8
#define OFF_WSV 0
#define OFF_WH  (48 * 64)                  // 3072
#define OFF_WMU (OFF_WH + VCIN * HH)       // 3344
#define OFF_WG  (OFF_WMU + HH * VV)        // 3600
#define OFF_BG  (OFF_WG + DD * VV)         // 4624
#define OFF_DST (OFF_BG + VV)              // 4640 (NWARP*EPW ints)
#define OFF_SCR (OFF_DST + NWARP * EPW)    // 4672 (16B aligned)
#define SMEM_FLOATS (OFF_SCR + NWARP * EPW * SCR)
#define SMEM_BYTES  (SMEM_FLOATS * 4)

__global__ __launch_bounds__(256) void edge_kernel(
    const float* __restrict__ ef, const float* __restrict__ xd,
    const float* __restrict__ dvec, const int* __restrict__ ei,
    const float* __restrict__ Wh, const float* __restrict__ WsV,
    const float* __restrict__ Wmu, const float* __restrict__ Wg,
    const float* __restrict__ bg)
{
    extern __shared__ float smem[];
    float* sWsV = smem + OFF_WSV;
    float* sWh  = smem + OFF_WH;
    float* sWmu = smem + OFF_WMU;
    float* sWg  = smem + OFF_WG;
    float* sbg  = smem + OFF_BG;

    const int t = threadIdx.x;
    for (int i = t; i < 48 * 64; i += 256) sWsV[i] = WsV[i];
    for (int i = t; i < VCIN * HH; i += 256) sWh[i] = Wh[i];
    if (t < HH * VV) sWmu[t] = Wmu[t];
    for (int i = t; i < DD * VV; i += 256) sWg[i] = Wg[i];
    if (t < VV) sbg[t] = bg[t];
    __syncthreads();

    const int warp = t >> 5, lane = t & 31;
    float* scr = smem + OFF_SCR + warp * EPW * SCR;
    int* sdstw = (int*)(smem + OFF_DST) + warp * EPW;

    const int hq  = lane >> 4;          // q-half within pass
    const int h16 = lane & 15;          // h (phase2) / o (phase5)
    const int q4  = lane >> 3, o0g = (lane & 7) * 2;  // gate roles

    const float inv_sigma = (float)NRBF / 10.0f;
    const float mu_step   = 10.0f / (float)(NRBF - 1);

    const int ntiles = NE / (NWARP * EPW);   // 25000 exact
    for (int tile = blockIdx.x; tile < ntiles; tile += gridDim.x) {
        const int ebase = tile * (NWARP * EPW) + warp * EPW;
        int srcs[EPW], dsts[EPW];

        // ---- Phase 1: rbf | ef | vin | meta ----
#pragma unroll
        for (int q = 0; q < EPW; q++) {
            const int e = ebase + q;
            float* X = scr + q * SCR;
            float* U = X + 96;
            srcs[q] = ei[e];
            dsts[q] = ei[NE + e];
            if (lane == 0) sdstw[q] = dsts[q];
            if (lane < 12) {
                float4 vv = *(const float4*)&g_v[(size_t)srcs[q] * 48 + lane * 4];
                *(float4*)&U[lane * 4] = vv;
            } else if (lane < 15) {
                U[36 + lane] = xd[e * 3 + (lane - 12)];   // U[48..50]
            }
            if (lane < 16) {
                float de = dvec[e];
                float tt = (de - (float)lane * mu_step) * inv_sigma;
                X[lane] = __expf(-tt * tt);
            } else {
                X[lane] = ef[e * NEF + (lane - 16)];      // X[16..31]
            }
        }
        __syncwarp();

        // ---- Phase 2: Vh + vnorm (lane = (q-half, h); 2 passes) ----
#pragma unroll
        for (int p = 0; p < 2; p++) {
            const int q = 2 * p + hq;
            float* X = scr + q * SCR;
            const float* U = X + 96;
            float vx = 0.f, vy = 0.f, vz = 0.f;
#pragma unroll
            for (int g = 0; g < 4; g++) {
                float4 u0 = *(const float4*)(U + 12 * g);
                float4 u1 = *(const float4*)(U + 12 * g + 4);
                float4 u2 = *(const float4*)(U + 12 * g + 8);
                float w;
                w = sWh[(4 * g + 0) * HH + h16]; vx += u0.x * w; vy += u0.y * w; vz += u0.z * w;
                w = sWh[(4 * g + 1) * HH + h16]; vx += u0.w * w; vy += u1.x * w; vz += u1.y * w;
                w = sWh[(4 * g + 2) * HH + h16]; vx += u1.z * w; vy += u1.w * w; vz += u2.x * w;
                w = sWh[(4 * g + 3) * HH + h16]; vx += u2.y * w; vy += u2.z * w; vz += u2.w * w;
            }
            {
                float w = sWh[16 * HH + h16];
                vx += U[48] * w; vy += U[49] * w; vz += U[50] * w;
            }
            float* Vh = X + 48;
            Vh[3 * h16]     = vx;
            Vh[3 * h16 + 1] = vy;
            Vh[3 * h16 + 2] = vz;
            X[32 + h16] = sqrtf(vx * vx + vy * vy + vz * vz + 1e-8f);
        }
        __syncwarp();

        // ---- Phase 3: sm = relu(P[src] + X @ WsV) ----
        const int j0 = 2 * lane;
        float acc[EPW][2];
#pragma unroll
        for (int q = 0; q < EPW; q++) {
            float2 p = *(const float2*)&g_P[(size_t)srcs[q] * 64 + j0];
            acc[q][0] = p.x; acc[q][1] = p.y;
        }
        {
            const float* X0 = scr;
            const float* X1 = scr + SCR;
            const float* X2 = scr + 2 * SCR;
            const float* X3 = scr + 3 * SCR;
#pragma unroll
            for (int k = 0; k < 48; k += 4) {
                float4 x0 = *(const float4*)(X0 + k);
                float4 x1 = *(const float4*)(X1 + k);
                float4 x2 = *(const float4*)(X2 + k);
                float4 x3 = *(const float4*)(X3 + k);
#pragma unroll
                for (int kk = 0; kk < 4; kk++) {
                    float2 w = *(const float2*)&sWsV[(k + kk) * DD + j0];
                    float a0 = ((const float*)&x0)[kk];
                    float a1 = ((const float*)&x1)[kk];
                    float a2 = ((const float*)&x2)[kk];
                    float a3 = ((const float*)&x3)[kk];
                    acc[0][0] += a0 * w.x; acc[0][1] += a0 * w.y;
                    acc[1][0] += a1 * w.x; acc[1][1] += a1 * w.y;
                    acc[2][0] += a2 * w.x; acc[2][1] += a2 * w.y;
                    acc[3][0] += a3 * w.x; acc[3][1] += a3 * w.y;
                }
            }
        }
#pragma unroll
        for (int q = 0; q < EPW; q++) {
            float* SM = scr + q * SCR + 96;
            *(float2*)&SM[j0] = make_float2(fmaxf(acc[q][0], 0.f), fmaxf(acc[q][1], 0.f));
        }
        __syncwarp();

        // ---- scatter sm (v4) ----
#pragma unroll
        for (int q = 0; q < EPW; q++) {
            if (lane < 16) {
                const float* SM = scr + q * SCR + 96;
                float4 v = *(const float4*)&SM[lane * 4];
                red_add_v4(&g_aggs[(size_t)dsts[q] * 64 + lane * 4], v.x, v.y, v.z, v.w);
            }
        }

        // ---- Phase 4: gate (lane = (q4, 2 cols)) ----
        {
            const float* SM = scr + q4 * SCR + 96;
            float a = sbg[o0g], b = sbg[o0g + 1];
#pragma unroll
            for (int j = 0; j < DD; j += 4) {
                float4 s4 = *(const float4*)&SM[j];
                float2 w0 = *(const float2*)&sWg[(j + 0) * VV + o0g];
                float2 w1 = *(const float2*)&sWg[(j + 1) * VV + o0g];
                float2 w2 = *(const float2*)&sWg[(j + 2) * VV + o0g];
                float2 w3 = *(const float2*)&sWg[(j + 3) * VV + o0g];
                a += s4.x * w0.x + s4.y * w1.x + s4.z * w2.x + s4.w * w3.x;
                b += s4.x * w0.y + s4.y * w1.y + s4.z * w2.y + s4.w * w3.y;
            }
            float* X = scr + q4 * SCR;
            X[o0g]     = 1.f / (1.f + __expf(-a));
            X[o0g + 1] = 1.f / (1.f + __expf(-b));
        }
        __syncwarp();

        // ---- Phase 5: vm = (Vh @ Wmu) * gate, direct red.v4 (2 passes) ----
#pragma unroll
        for (int p = 0; p < 2; p++) {
            const int q = 2 * p + hq;
            const float* X  = scr + q * SCR;
            const float* Vh = X + 48;
            float vx = 0.f, vy = 0.f, vz = 0.f;
#pragma unroll
            for (int g = 0; g < 4; g++) {
                float4 u0 = *(const float4*)(Vh + 12 * g);
                float4 u1 = *(const float4*)(Vh + 12 * g + 4);
                float4 u2 = *(const float4*)(Vh + 12 * g + 8);
                float w;
                w = sWmu[(4 * g + 0) * VV + h16]; vx += u0.x * w; vy += u0.y * w; vz += u0.z * w;
                w = sWmu[(4 * g + 1) * VV + h16]; vx += u0.w * w; vy += u1.x * w; vz += u1.y * w;
                w = sWmu[(4 * g + 2) * VV + h16]; vx += u1.z * w; vy += u1.w * w; vz += u2.x * w;
                w = sWmu[(4 * g + 3) * VV + h16]; vx += u2.y * w; vy += u2.z * w; vz += u2.w * w;
            }
            float gt = X[h16];
            int dst = sdstw[q];
            red_add_v4(&g_aggv[(size_t)dst * 64 + h16 * 4],
                       vx * gt, vy * gt, vz * gt, 0.f);
        }
        __syncwarp();
    }
}

// ---------------- fused update (+ optional next-layer P GEMM) ----------------
__global__ __launch_bounds__(256) void update_pre_kernel(
    const float* __restrict__ WsPnext, const float* __restrict__ bsnext,
    float* __restrict__ out, int do_pre)
{
    __shared__ float sW[64 * 64];
    __shared__ float sS[32 * 65];
    const int t = threadIdx.x;
    const int nb = blockIdx.x * 32;
    const int nl = t >> 3, j0 = (t & 7) * 8;
    const int node = nb + nl;

    // s residual update -> g_s (+ out), stage into sS
    if (node < NN) {
        float inv = g_invdeg[node];
        float4 s0 = *(const float4*)&g_s[(size_t)node * 64 + j0];
        float4 s1 = *(const float4*)&g_s[(size_t)node * 64 + j0 + 4];
        float4 a0 = *(const float4*)&g_aggs[(size_t)node * 64 + j0];
        float4 a1 = *(const float4*)&g_aggs[(size_t)node * 64 + j0 + 4];
        s0.x += a0.x * inv; s0.y += a0.y * inv; s0.z += a0.z * inv; s0.w += a0.w * inv;
        s1.x += a1.x * inv; s1.y += a1.y * inv; s1.z += a1.z * inv; s1.w += a1.w * inv;
        *(float4*)&g_s[(size_t)node * 64 + j0]     = s0;
        *(float4*)&g_s[(size_t)node * 64 + j0 + 4] = s1;
        if (out) {
            *(float4*)&out[(size_t)node * 64 + j0]     = s0;
            *(float4*)&out[(size_t)node * 64 + j0 + 4] = s1;
        }
        sS[nl * 65 + j0]     = s0.x; sS[nl * 65 + j0 + 1] = s0.y;
        sS[nl * 65 + j0 + 2] = s0.z; sS[nl * 65 + j0 + 3] = s0.w;
        sS[nl * 65 + j0 + 4] = s1.x; sS[nl * 65 + j0 + 5] = s1.y;
        sS[nl * 65 + j0 + 6] = s1.z; sS[nl * 65 + j0 + 7] = s1.w;
    } else {
#pragma unroll
        for (int k = 0; k < 8; k++) sS[nl * 65 + j0 + k] = 0.f;
    }

    // v residual update
    for (int j = t; j < 32 * 48; j += 256) {
        int n2 = j / 48, r = j - n2 * 48;
        int gn = nb + n2;
        if (gn < NN) {
            int o = r / 3, d = r - 3 * o;
            g_v[(size_t)gn * 48 + r] += g_aggv[(size_t)gn * 64 + o * 4 + d] * g_invdeg[gn];
        }
    }

    if (!do_pre) return;

    for (int i = t; i < 64 * 64; i += 256) sW[i] = WsPnext[i];
    __syncthreads();

    float4 a0 = *(const float4*)(bsnext + j0);
    float4 a1 = *(const float4*)(bsnext + j0 + 4);
#pragma unroll 8
    for (int k = 0; k < 64; k++) {
        float a = sS[nl * 65 + k];
        float4 w0 = *(const float4*)&sW[k * 64 + j0];
        float4 w1 = *(const float4*)&sW[k * 64 + j0 + 4];
        a0.x += a * w0.x; a0.y += a * w0.y; a0.z += a * w0.z; a0.w += a * w0.w;
        a1.x += a * w1.x; a1.y += a * w1.y; a1.z += a * w1.z; a1.w += a * w1.w;
    }
    if (node < NN) {
        *(float4*)&g_P[(size_t)node * 64 + j0]     = a0;
        *(float4*)&g_P[(size_t)node * 64 + j0 + 4] = a1;
    }
}

extern "C" void kernel_launch(void* const* d_in, const int* in_sizes, int n_in,
                              void* d_out, int out_size)
{
    const float* sf  = (const float*)d_in[0];
    const float* vf  = (const float*)d_in[2];
    const float* ef  = (const float*)d_in[3];
    const float* xd  = (const float*)d_in[4];
    const float* dv  = (const float*)d_in[5];
    const int*   eix = (const int*)  d_in[6];
    const float* W1  = (const float*)d_in[7];
    const float* b1  = (const float*)d_in[8];
    const float* W2  = (const float*)d_in[9];
    const float* b2  = (const float*)d_in[10];
    const float* Wh  = (const float*)d_in[11];
    const float* Ws  = (const float*)d_in[12];
    const float* bs  = (const float*)d_in[13];
    const float* Wmu = (const float*)d_in[14];
    const float* Wg  = (const float*)d_in[15];
    const float* bg  = (const float*)d_in[16];
    (void)in_sizes; (void)n_in; (void)out_size;

    cudaFuncSetAttribute(edge_kernel,
                         cudaFuncAttributeMaxDynamicSharedMemorySize, SMEM_BYTES);

    void *p_deg = nullptr, *p_aggs = nullptr, *p_aggv = nullptr;
    cudaGetSymbolAddress(&p_deg,  g_deg);
    cudaGetSymbolAddress(&p_aggs, g_aggs);
    cudaGetSymbolAddress(&p_aggv, g_aggv);

    embed_kernel<<<(NN + 7) / 8, 128>>>(sf, W1, b1, W2, b2, vf);
    cudaMemsetAsync(p_deg, 0, NN * sizeof(float));
    deg_kernel<<<(NE + 255) / 256, 256>>>(eix);
    invdeg_kernel<<<(NN + 255) / 256, 256>>>();
    pre_kernel<<<(NN + 31) / 32, 256>>>(Ws, bs);   // layer-0 P

    const int nblk = (NN + 31) / 32;
    for (int l = 0; l < NLAYER; l++) {
        cudaMemsetAsync(p_aggs, 0, (size_t)NN * 64 * sizeof(float));
        cudaMemsetAsync(p_aggv, 0, (size_t)NN * 64 * sizeof(float));
        edge_kernel<<<740, 256, SMEM_BYTES>>>(
            ef, xd, dv, eix,
            Wh  + l * VCIN * HH,
            Ws  + (size_t)l * 112 * 64 + 64 * 64,
            Wmu + l * HH * VV,
            Wg  + l * DD * VV,
            bg  + l * VV);
        int last = (l == NLAYER - 1);
        update_pre_kernel<<<nblk, 256>>>(
            last ? Ws : Ws + (size_t)(l + 1) * 112 * 64,
            last ? bs : bs + (l + 1) * DD,
            last ? (float*)d_out : nullptr,
            last ? 0 : 1);
    }
}

// round 8
// speedup vs baseline: 2.2732x; 1.3960x over previous
#include <cuda_runtime.h>
#include <cuda_bf16.h>

#define S_IN   44
#define HID    128
#define DD     64
#define VV     16
#define HH     16
#define NRBF   16
#define NEF    16
#define VCIN   17
#define NN     50000
#define NE     800000
#define NLAYER 3

__device__ float g_s[NN * DD];
__device__ float g_v[NN * VV * 3];
__device__ float g_P[NN * DD];        // per-layer: s@Ws[0:64]+bs
__device__ float g_Vn[NN * 64];       // per-layer: [n][h*4 + {x,y,z,nsq}]
__device__ float g_Mn[NN * 64];       // per-layer: [n][o*4 + {x,y,z,-}]
__device__ float g_aggs[NN * DD];
__device__ float g_aggv[NN * 64];     // padded [node][o:16][4]
__device__ float g_deg[NN];
__device__ float g_invdeg[NN];

__device__ __forceinline__ void red_add_v4(float* p, float a, float b, float c, float d)
{
    asm volatile("red.global.add.v4.f32 [%0], {%1,%2,%3,%4};"
                 :: "l"(p), "f"(a), "f"(b), "f"(c), "f"(d) : "memory");
}

// ---------------- node embedding ----------------
__global__ __launch_bounds__(128) void embed_kernel(
    const float* __restrict__ sf, const float* __restrict__ W1,
    const float* __restrict__ b1, const float* __restrict__ W2,
    const float* __restrict__ b2, const float* __restrict__ vf)
{
    __shared__ float ssf[8][S_IN];
    __shared__ float sh[8][HID];
    const int nb = blockIdx.x * 8;
    const int t  = threadIdx.x;

    for (int i = t; i < 8 * S_IN; i += 128) {
        int n = i / S_IN, k = i - n * S_IN;
        int node = nb + n;
        ssf[n][k] = (node < NN) ? sf[node * S_IN + k] : 0.f;
    }
    __syncthreads();

    float acc[8];
    float bb = b1[t];
#pragma unroll
    for (int n = 0; n < 8; n++) acc[n] = bb;
    for (int k = 0; k < S_IN; k++) {
        float w = W1[k * HID + t];
#pragma unroll
        for (int n = 0; n < 8; n++) acc[n] += ssf[n][k] * w;
    }
#pragma unroll
    for (int n = 0; n < 8; n++) sh[n][t] = fmaxf(acc[n], 0.f);
    __syncthreads();

    if (t < DD) {
        float acc2[8];
        float b2v = b2[t];
#pragma unroll
        for (int n = 0; n < 8; n++) acc2[n] = b2v;
        for (int k = 0; k < HID; k++) {
            float w = W2[k * DD + t];
#pragma unroll
            for (int n = 0; n < 8; n++) acc2[n] += sh[n][k] * w;
        }
#pragma unroll
        for (int n = 0; n < 8; n++)
            if (nb + n < NN) g_s[(nb + n) * DD + t] = acc2[n];
    }
    for (int i = t; i < 8 * VV * 3; i += 128) {
        int n = i / (VV * 3), k = i - n * (VV * 3);
        int node = nb + n;
        if (node < NN) g_v[node * VV * 3 + k] = vf[node * VV * 3 + k];
    }
}

__global__ void deg_kernel(const int* __restrict__ ei)
{
    int e = blockIdx.x * blockDim.x + threadIdx.x;
    if (e < NE) atomicAdd(&g_deg[ei[NE + e]], 1.0f);
}
__global__ void invdeg_kernel()
{
    int i = blockIdx.x * blockDim.x + threadIdx.x;
    if (i < NN) g_invdeg[i] = 1.0f / fmaxf(g_deg[i], 1.0f);
}

// ---------------- edge kernel ----------------
// per-edge scratch SCR=116 floats (stripes {0,20,8,28} mod 32, conflict-free):
//  [0:16] rbf -> gate   [16:32] ef   [32:48] vnorm   [48:51] xd   [52:116] SM
#define EPW 4
#define SCR 116
#define NWARP 8
#define OFF_WSV  0                       // 48*64 = 3072
#define OFF_WGT  3072                    // 16*68 = 1088 (Wg transposed, stride 68)
#define OFF_BG   4160                    // 16
#define OFF_WH16 4176                    // 16
#define OFF_WMUX 4192                    // 16
#define OFF_SRC  4208                    // 32 ints
#define OFF_DST  4240                    // 32 ints
#define OFF_SCR  4272                    // 4272*4 % 16 == 0
#define SMEM_FLOATS (OFF_SCR + NWARP * EPW * SCR)
#define SMEM_BYTES  (SMEM_FLOATS * 4)

__global__ __launch_bounds__(256) void edge_kernel(
    const float* __restrict__ ef, const float* __restrict__ xd,
    const float* __restrict__ dvec, const int* __restrict__ ei,
    const float* __restrict__ Wh, const float* __restrict__ WsV,
    const float* __restrict__ Wmu, const float* __restrict__ Wg,
    const float* __restrict__ bg, int compute_vm)
{
    extern __shared__ float smem[];
    float* sWsV  = smem + OFF_WSV;
    float* sWgT  = smem + OFF_WGT;
    float* sbg   = smem + OFF_BG;
    float* swh16 = smem + OFF_WH16;
    float* swmux = smem + OFF_WMUX;

    const int t = threadIdx.x;
    for (int i = t; i < 48 * 64; i += 256) sWsV[i] = WsV[i];
    for (int i = t; i < 16 * 64; i += 256) {
        int j = i >> 4, o = i & 15;            // Wg[j][o]
        sWgT[o * 68 + j] = Wg[i];
    }
    if (t < 16) {
        sbg[t]   = bg[t];
        swh16[t] = Wh[16 * HH + t];
        float a = 0.f;
#pragma unroll
        for (int h = 0; h < HH; h++) a += Wh[16 * HH + h] * Wmu[h * VV + t];
        swmux[t] = a;
    }
    __syncthreads();

    const int warp = t >> 5, lane = t & 31;
    float* scr = smem + OFF_SCR + warp * EPW * SCR;
    int* ssrcw = (int*)(smem + OFF_SRC) + warp * EPW;
    int* sdstw = (int*)(smem + OFF_DST) + warp * EPW;

    const int hq  = lane >> 4;                  // half-warp id
    const int h16 = lane & 15;                  // h / o role
    const int q4  = lane >> 3, o0g = (lane & 7) * 2;

    const float inv_sigma = (float)NRBF / 10.0f;
    const float mu_step   = 10.0f / (float)(NRBF - 1);

    const int ntiles = NE / (NWARP * EPW);      // 25000 exact
    for (int tile = blockIdx.x; tile < ntiles; tile += gridDim.x) {
        const int ebase = tile * (NWARP * EPW) + warp * EPW;
        int srcs[EPW], dsts[EPW];

        if (lane < EPW) {
            ssrcw[lane] = ei[ebase + lane];
            sdstw[lane] = ei[NE + ebase + lane];
        }
        // ---- Phase 1: rbf | ef | xd ----
#pragma unroll
        for (int q = 0; q < EPW; q++) {
            const int e = ebase + q;
            float* X = scr + q * SCR;
            srcs[q] = ei[e];
            dsts[q] = ei[NE + e];
            if (lane < 16) {
                float de = dvec[e];
                float tt = (de - (float)lane * mu_step) * inv_sigma;
                X[lane] = __expf(-tt * tt);
            } else {
                X[lane] = ef[e * NEF + (lane - 16)];
            }
            if (lane >= 29) X[48 + lane - 29] = xd[e * 3 + (lane - 29)];
        }
        __syncwarp();

        // ---- Phase 2: vnorm from hoisted Vn/nsq (2 passes, lane=(hq,h16)) ----
#pragma unroll
        for (int p = 0; p < 2; p++) {
            const int q = 2 * p + hq;
            float* X = scr + q * SCR;
            const int src = ssrcw[q];
            float4 vn = *(const float4*)&g_Vn[(size_t)src * 64 + h16 * 4];
            float x0 = X[48], x1 = X[49], x2 = X[50];
            float dot = vn.x * x0 + vn.y * x1 + vn.z * x2;
            float xsq = x0 * x0 + x1 * x1 + x2 * x2;
            float w = swh16[h16];
            X[32 + h16] = sqrtf(vn.w + 2.f * w * dot + w * w * xsq + 1e-8f);
        }
        __syncwarp();

        // ---- Phase 3: sm = relu(P[src] + X @ WsV) ----
        const int j0 = 2 * lane;
        float acc[EPW][2];
#pragma unroll
        for (int q = 0; q < EPW; q++) {
            float2 p = *(const float2*)&g_P[(size_t)srcs[q] * 64 + j0];
            acc[q][0] = p.x; acc[q][1] = p.y;
        }
        {
            const float* X0 = scr;
            const float* X1 = scr + SCR;
            const float* X2 = scr + 2 * SCR;
            const float* X3 = scr + 3 * SCR;
#pragma unroll
            for (int k = 0; k < 48; k += 4) {
                float4 x0 = *(const float4*)(X0 + k);
                float4 x1 = *(const float4*)(X1 + k);
                float4 x2 = *(const float4*)(X2 + k);
                float4 x3 = *(const float4*)(X3 + k);
#pragma unroll
                for (int kk = 0; kk < 4; kk++) {
                    float2 w = *(const float2*)&sWsV[(k + kk) * DD + j0];
                    float a0 = ((const float*)&x0)[kk];
                    float a1 = ((const float*)&x1)[kk];
                    float a2 = ((const float*)&x2)[kk];
                    float a3 = ((const float*)&x3)[kk];
                    acc[0][0] += a0 * w.x; acc[0][1] += a0 * w.y;
                    acc[1][0] += a1 * w.x; acc[1][1] += a1 * w.y;
                    acc[2][0] += a2 * w.x; acc[2][1] += a2 * w.y;
                    acc[3][0] += a3 * w.x; acc[3][1] += a3 * w.y;
                }
            }
        }
#pragma unroll
        for (int q = 0; q < EPW; q++) {
            float* SM = scr + q * SCR + 52;
            *(float2*)&SM[j0] = make_float2(fmaxf(acc[q][0], 0.f), fmaxf(acc[q][1], 0.f));
        }
        __syncwarp();

        // ---- scatter sm (v4) ----
#pragma unroll
        for (int q = 0; q < EPW; q++) {
            if (lane < 16) {
                const float* SM = scr + q * SCR + 52;
                float4 v = *(const float4*)&SM[lane * 4];
                red_add_v4(&g_aggs[(size_t)dsts[q] * 64 + lane * 4], v.x, v.y, v.z, v.w);
            }
        }

        if (compute_vm) {
            // ---- Phase 4: gate (lane=(q4, 2 cols), transposed Wg stride 68) ----
            {
                const float* SM = scr + q4 * SCR + 52;
                float a = sbg[o0g], b = sbg[o0g + 1];
#pragma unroll
                for (int j = 0; j < DD; j += 4) {
                    float4 s4 = *(const float4*)&SM[j];
                    float4 wa = *(const float4*)&sWgT[o0g * 68 + j];
                    float4 wb = *(const float4*)&sWgT[(o0g + 1) * 68 + j];
                    a += s4.x * wa.x + s4.y * wa.y + s4.z * wa.z + s4.w * wa.w;
                    b += s4.x * wb.x + s4.y * wb.y + s4.z * wb.z + s4.w * wb.w;
                }
                float* X = scr + q4 * SCR;
                X[o0g]     = 1.f / (1.f + __expf(-a));
                X[o0g + 1] = 1.f / (1.f + __expf(-b));
            }
            __syncwarp();

            // ---- Phase 5: vm = (Mn[src] + xd*wmux) * gate, direct red.v4 ----
#pragma unroll
            for (int p = 0; p < 2; p++) {
                const int q = 2 * p + hq;
                const float* X = scr + q * SCR;
                const int src = ssrcw[q];
                const int dst = sdstw[q];
                float4 mn = *(const float4*)&g_Mn[(size_t)src * 64 + h16 * 4];
                float x0 = X[48], x1 = X[49], x2 = X[50];
                float gt = X[h16];
                float wm = swmux[h16];
                red_add_v4(&g_aggv[(size_t)dst * 64 + h16 * 4],
                           (mn.x + x0 * wm) * gt,
                           (mn.y + x1 * wm) * gt,
                           (mn.z + x2 * wm) * gt, 0.f);
            }
        }
        __syncwarp();
    }
}

// ---------------- fused update + per-node precompute ----------------
// mode: 0 = init (no residual updates), 1 = mid (update s,v), 2 = last (s only + out)
__global__ __launch_bounds__(256) void update_pre_kernel(
    const float* __restrict__ WsPnext, const float* __restrict__ bsnext,
    const float* __restrict__ Wh, const float* __restrict__ Wmu,
    float* __restrict__ out, int mode, int do_mn)
{
    __shared__ float sW[64 * 64];
    __shared__ float sS[32 * 65];
    __shared__ float sv[32 * 48];
    __shared__ float sVn[32 * 64];
    __shared__ float sWh[16 * 16];
    __shared__ float sWm[16 * 16];

    const int t = threadIdx.x;
    const int nb = blockIdx.x * 32;
    const int nl = t >> 3, j0 = (t & 7) * 8;
    const int node = nb + nl;

    // ---- s path ----
    if (node < NN) {
        float4 s0 = *(const float4*)&g_s[(size_t)node * 64 + j0];
        float4 s1 = *(const float4*)&g_s[(size_t)node * 64 + j0 + 4];
        if (mode != 0) {
            float inv = g_invdeg[node];
            float4 a0 = *(const float4*)&g_aggs[(size_t)node * 64 + j0];
            float4 a1 = *(const float4*)&g_aggs[(size_t)node * 64 + j0 + 4];
            s0.x += a0.x * inv; s0.y += a0.y * inv; s0.z += a0.z * inv; s0.w += a0.w * inv;
            s1.x += a1.x * inv; s1.y += a1.y * inv; s1.z += a1.z * inv; s1.w += a1.w * inv;
            *(float4*)&g_s[(size_t)node * 64 + j0]     = s0;
            *(float4*)&g_s[(size_t)node * 64 + j0 + 4] = s1;
            if (mode == 2) {
                *(float4*)&out[(size_t)node * 64 + j0]     = s0;
                *(float4*)&out[(size_t)node * 64 + j0 + 4] = s1;
            }
        }
        sS[nl * 65 + j0]     = s0.x; sS[nl * 65 + j0 + 1] = s0.y;
        sS[nl * 65 + j0 + 2] = s0.z; sS[nl * 65 + j0 + 3] = s0.w;
        sS[nl * 65 + j0 + 4] = s1.x; sS[nl * 65 + j0 + 5] = s1.y;
        sS[nl * 65 + j0 + 6] = s1.z; sS[nl * 65 + j0 + 7] = s1.w;
    } else {
#pragma unroll
        for (int k = 0; k < 8; k++) sS[nl * 65 + j0 + k] = 0.f;
    }
    if (mode == 2) return;

    // ---- v path ----
    for (int i = t; i < 32 * 48; i += 256) {
        int n2 = i / 48, r = i - n2 * 48;
        int gn = nb + n2;
        float vv = 0.f;
        if (gn < NN) {
            vv = g_v[(size_t)gn * 48 + r];
            if (mode == 1) {
                int o = r / 3, d = r - 3 * o;
                vv += g_aggv[(size_t)gn * 64 + o * 4 + d] * g_invdeg[gn];
                g_v[(size_t)gn * 48 + r] = vv;
            }
        }
        sv[n2 * 48 + r] = vv;
    }

    for (int i = t; i < 64 * 64; i += 256) sW[i] = WsPnext[i];
    if (t < 256) { sWh[t] = Wh[t]; sWm[t] = Wmu[t]; }
    __syncthreads();

    // ---- P GEMM ----
    {
        float4 a0 = *(const float4*)(bsnext + j0);
        float4 a1 = *(const float4*)(bsnext + j0 + 4);
#pragma unroll 8
        for (int k = 0; k < 64; k++) {
            float a = sS[nl * 65 + k];
            float4 w0 = *(const float4*)&sW[k * 64 + j0];
            float4 w1 = *(const float4*)&sW[k * 64 + j0 + 4];
            a0.x += a * w0.x; a0.y += a * w0.y; a0.z += a * w0.z; a0.w += a * w0.w;
            a1.x += a * w1.x; a1.y += a * w1.y; a1.z += a * w1.z; a1.w += a * w1.w;
        }
        if (node < NN) {
            *(float4*)&g_P[(size_t)node * 64 + j0]     = a0;
            *(float4*)&g_P[(size_t)node * 64 + j0 + 4] = a1;
        }
    }

    // ---- Vn = v @ Wh[0:16] ----
    for (int i = t; i < 32 * 48; i += 256) {
        int n = i / 48, r = i - n * 48;
        int h = r / 3, d = r - 3 * h;
        float a = 0.f;
#pragma unroll
        for (int c = 0; c < 16; c++) a += sv[n * 48 + c * 3 + d] * sWh[c * 16 + h];
        sVn[n * 64 + h * 4 + d] = a;
    }
    __syncthreads();

    // ---- nsq + write g_Vn ----
    for (int i = t; i < 32 * 16; i += 256) {
        int n = i >> 4, h = i & 15;
        int gn = nb + n;
        if (gn < NN) {
            float a = sVn[n * 64 + h * 4];
            float b = sVn[n * 64 + h * 4 + 1];
            float c = sVn[n * 64 + h * 4 + 2];
            *(float4*)&g_Vn[(size_t)gn * 64 + h * 4] =
                make_float4(a, b, c, a * a + b * b + c * c);
        }
    }

    // ---- Mn = Vn @ Wmu ----
    if (do_mn) {
        for (int i = t; i < 32 * 48; i += 256) {
            int n = i / 48, r = i - n * 48;
            int o = r / 3, d = r - 3 * o;
            int gn = nb + n;
            if (gn < NN) {
                float a = 0.f;
#pragma unroll
                for (int h = 0; h < 16; h++) a += sVn[n * 64 + h * 4 + d] * sWm[h * 16 + o];
                g_Mn[(size_t)gn * 64 + o * 4 + d] = a;
            }
        }
    }
}

extern "C" void kernel_launch(void* const* d_in, const int* in_sizes, int n_in,
                              void* d_out, int out_size)
{
    const float* sf  = (const float*)d_in[0];
    const float* vf  = (const float*)d_in[2];
    const float* ef  = (const float*)d_in[3];
    const float* xd  = (const float*)d_in[4];
    const float* dv  = (const float*)d_in[5];
    const int*   eix = (const int*)  d_in[6];
    const float* W1  = (const float*)d_in[7];
    const float* b1  = (const float*)d_in[8];
    const float* W2  = (const float*)d_in[9];
    const float* b2  = (const float*)d_in[10];
    const float* Wh  = (const float*)d_in[11];
    const float* Ws  = (const float*)d_in[12];
    const float* bs  = (const float*)d_in[13];
    const float* Wmu = (const float*)d_in[14];
    const float* Wg  = (const float*)d_in[15];
    const float* bg  = (const float*)d_in[16];
    (void)in_sizes; (void)n_in; (void)out_size;

    cudaFuncSetAttribute(edge_kernel,
                         cudaFuncAttributeMaxDynamicSharedMemorySize, SMEM_BYTES);

    void *p_deg = nullptr, *p_aggs = nullptr, *p_aggv = nullptr;
    cudaGetSymbolAddress(&p_deg,  g_deg);
    cudaGetSymbolAddress(&p_aggs, g_aggs);
    cudaGetSymbolAddress(&p_aggv, g_aggv);

    embed_kernel<<<(NN + 7) / 8, 128>>>(sf, W1, b1, W2, b2, vf);
    cudaMemsetAsync(p_deg, 0, NN * sizeof(float));
    deg_kernel<<<(NE + 255) / 256, 256>>>(eix);
    invdeg_kernel<<<(NN + 255) / 256, 256>>>();

    const int nblk = (NN + 31) / 32;
    // init: P0, Vn0, Mn0 (layer-0 weights)
    update_pre_kernel<<<nblk, 256>>>(Ws, bs, Wh, Wmu, nullptr, 0, 1);

    for (int l = 0; l < NLAYER; l++) {
        int vm = (l < NLAYER - 1);
        cudaMemsetAsync(p_aggs, 0, (size_t)NN * 64 * sizeof(float));
        if (vm) cudaMemsetAsync(p_aggv, 0, (size_t)NN * 64 * sizeof(float));
        edge_kernel<<<1036, 256, SMEM_BYTES>>>(
            ef, xd, dv, eix,
            Wh  + l * VCIN * HH,
            Ws  + (size_t)l * 112 * 64 + 64 * 64,
            Wmu + l * HH * VV,
            Wg  + l * DD * VV,
            bg  + l * VV, vm);
        if (l < NLAYER - 1) {
            int ln = l + 1;
            update_pre_kernel<<<nblk, 256>>>(
                Ws + (size_t)ln * 112 * 64, bs + ln * DD,
                Wh + ln * VCIN * HH, Wmu + ln * HH * VV,
                nullptr, 1, (ln < NLAYER - 1) ? 1 : 0);
        } else {
            update_pre_kernel<<<nblk, 256>>>(
                Ws, bs, Wh, Wmu, (float*)d_out, 2, 0);
        }
    }
}

// round 9
// speedup vs baseline: 2.7543x; 1.2116x over previous
#include <cuda_runtime.h>
#include <cuda_bf16.h>

#define S_IN   44
#define HID    128
#define DD     64
#define VV     16
#define HH     16
#define NRBF   16
#define NEF    16
#define VCIN   17
#define NN     50000
#define NE     800000
#define NLAYER 3

__device__ float g_s[NN * DD];
__device__ float g_v[NN * VV * 3];
__device__ float g_P[NN * DD];        // per-layer: s@Ws[0:64]+bs
__device__ float g_Vn[NN * 64];       // per-layer: [n][h*4 + {x,y,z,nsq}]
__device__ float g_Mn[NN * 64];       // per-layer: [n][o*4 + {x,y,z,-}]
__device__ float g_aggs[NN * DD];
__device__ float g_aggv[NN * 64];     // padded [node][o:16][4]
__device__ float g_deg[NN];
__device__ float g_invdeg[NN];

__device__ __forceinline__ void red_add_v4(float* p, float a, float b, float c, float d)
{
    asm volatile("red.global.add.v4.f32 [%0], {%1,%2,%3,%4};"
                 :: "l"(p), "f"(a), "f"(b), "f"(c), "f"(d) : "memory");
}

// ---------------- node embedding ----------------
__global__ __launch_bounds__(128) void embed_kernel(
    const float* __restrict__ sf, const float* __restrict__ W1,
    const float* __restrict__ b1, const float* __restrict__ W2,
    const float* __restrict__ b2, const float* __restrict__ vf)
{
    __shared__ float ssf[8][S_IN];
    __shared__ float sh[8][HID];
    const int nb = blockIdx.x * 8;
    const int t  = threadIdx.x;

    for (int i = t; i < 8 * S_IN; i += 128) {
        int n = i / S_IN, k = i - n * S_IN;
        int node = nb + n;
        ssf[n][k] = (node < NN) ? sf[node * S_IN + k] : 0.f;
    }
    __syncthreads();

    float acc[8];
    float bb = b1[t];
#pragma unroll
    for (int n = 0; n < 8; n++) acc[n] = bb;
    for (int k = 0; k < S_IN; k++) {
        float w = W1[k * HID + t];
#pragma unroll
        for (int n = 0; n < 8; n++) acc[n] += ssf[n][k] * w;
    }
#pragma unroll
    for (int n = 0; n < 8; n++) sh[n][t] = fmaxf(acc[n], 0.f);
    __syncthreads();

    if (t < DD) {
        float acc2[8];
        float b2v = b2[t];
#pragma unroll
        for (int n = 0; n < 8; n++) acc2[n] = b2v;
        for (int k = 0; k < HID; k++) {
            float w = W2[k * DD + t];
#pragma unroll
            for (int n = 0; n < 8; n++) acc2[n] += sh[n][k] * w;
        }
#pragma unroll
        for (int n = 0; n < 8; n++)
            if (nb + n < NN) g_s[(nb + n) * DD + t] = acc2[n];
    }
    for (int i = t; i < 8 * VV * 3; i += 128) {
        int n = i / (VV * 3), k = i - n * (VV * 3);
        int node = nb + n;
        if (node < NN) g_v[node * VV * 3 + k] = vf[node * VV * 3 + k];
    }
}

__global__ void deg_kernel(const int* __restrict__ ei)
{
    int e = blockIdx.x * blockDim.x + threadIdx.x;
    if (e < NE) atomicAdd(&g_deg[ei[NE + e]], 1.0f);
}
__global__ void invdeg_kernel()
{
    int i = blockIdx.x * blockDim.x + threadIdx.x;
    if (i < NN) g_invdeg[i] = 1.0f / fmaxf(g_deg[i], 1.0f);
}

// ---------------- edge kernel: warp = 8 edges ----------------
// per-edge scratch SCR=116 floats (stripes all-distinct mod 32):
//  [0:16] rbf -> gate   [16:32] ef   [32:48] vnorm   [48:51] xd   [52:116] SM
#define EPW 8
#define SCR 116
#define NWARP 8
#define OFF_WSV  0                       // 48*64 = 3072
#define OFF_WGT  3072                    // 16*68 = 1088 (Wg transposed, stride 68)
#define OFF_BG   4160                    // 16
#define OFF_WH16 4176                    // 16
#define OFF_WMUX 4192                    // 16
#define OFF_SRC  4208                    // 64 ints
#define OFF_DST  4272                    // 64 ints
#define OFF_SCR  4336                    // 4336*4 % 16 == 0
#define SMEM_FLOATS (OFF_SCR + NWARP * EPW * SCR)
#define SMEM_BYTES  (SMEM_FLOATS * 4)

__global__ __launch_bounds__(256) void edge_kernel(
    const float* __restrict__ ef, const float* __restrict__ xd,
    const float* __restrict__ dvec, const int* __restrict__ ei,
    const float* __restrict__ Wh, const float* __restrict__ WsV,
    const float* __restrict__ Wmu, const float* __restrict__ Wg,
    const float* __restrict__ bg, int compute_vm)
{
    extern __shared__ float smem[];
    float* sWsV  = smem + OFF_WSV;
    float* sWgT  = smem + OFF_WGT;
    float* sbg   = smem + OFF_BG;
    float* swh16 = smem + OFF_WH16;
    float* swmux = smem + OFF_WMUX;

    const int t = threadIdx.x;
    for (int i = t; i < 48 * 64; i += 256) sWsV[i] = WsV[i];
    for (int i = t; i < 16 * 64; i += 256) {
        int j = i >> 4, o = i & 15;            // Wg[j][o]
        sWgT[o * 68 + j] = Wg[i];
    }
    if (t < 16) {
        sbg[t]   = bg[t];
        swh16[t] = Wh[16 * HH + t];
        float a = 0.f;
#pragma unroll
        for (int h = 0; h < HH; h++) a += Wh[16 * HH + h] * Wmu[h * VV + t];
        swmux[t] = a;
    }
    __syncthreads();

    const int warp = t >> 5, lane = t & 31;
    float* scr = smem + OFF_SCR + warp * EPW * SCR;
    int* ssrcw = (int*)(smem + OFF_SRC) + warp * EPW;
    int* sdstw = (int*)(smem + OFF_DST) + warp * EPW;

    const int hq  = lane >> 4;                  // half-warp id
    const int h16 = lane & 15;                  // h / o role
    const int q3  = lane >> 2, cg = lane & 3;   // gate roles: edge q3, col class cg

    const float inv_sigma = (float)NRBF / 10.0f;
    const float mu_step   = 10.0f / (float)(NRBF - 1);

    const int ntiles = NE / (NWARP * EPW);      // 12500 exact
    for (int tile = blockIdx.x; tile < ntiles; tile += gridDim.x) {
        const int ebase = tile * (NWARP * EPW) + warp * EPW;

        if (lane < EPW) {
            ssrcw[lane] = ei[ebase + lane];
            sdstw[lane] = ei[NE + ebase + lane];
        }
        // ---- Phase 1: rbf | ef | xd ----
#pragma unroll
        for (int q = 0; q < EPW; q++) {
            const int e = ebase + q;
            float* X = scr + q * SCR;
            if (lane < 16) {
                float de = dvec[e];
                float tt = (de - (float)lane * mu_step) * inv_sigma;
                X[lane] = __expf(-tt * tt);
            } else {
                X[lane] = ef[e * NEF + (lane - 16)];
            }
            if (lane >= 29) X[48 + lane - 29] = xd[e * 3 + (lane - 29)];
        }
        __syncwarp();

        // ---- Phase 2: vnorm from hoisted Vn/nsq (4 passes, lane=(hq,h16)) ----
#pragma unroll
        for (int p = 0; p < 4; p++) {
            const int q = 2 * p + hq;
            float* X = scr + q * SCR;
            const int src = ssrcw[q];
            float4 vn = *(const float4*)&g_Vn[(size_t)src * 64 + h16 * 4];
            float x0 = X[48], x1 = X[49], x2 = X[50];
            float dot = vn.x * x0 + vn.y * x1 + vn.z * x2;
            float xsq = x0 * x0 + x1 * x1 + x2 * x2;
            float w = swh16[h16];
            X[32 + h16] = sqrtf(vn.w + 2.f * w * dot + w * w * xsq + 1e-8f);
        }
        __syncwarp();

        // ---- Phase 3: sm = relu(P[src] + X @ WsV), 8 edges jointly ----
        const int j0 = 2 * lane;
        float acc[EPW][2];
#pragma unroll
        for (int q = 0; q < EPW; q++) {
            float2 p = *(const float2*)&g_P[(size_t)ssrcw[q] * 64 + j0];
            acc[q][0] = p.x; acc[q][1] = p.y;
        }
#pragma unroll
        for (int k = 0; k < 48; k += 4) {
            float2 w0 = *(const float2*)&sWsV[(k + 0) * DD + j0];
            float2 w1 = *(const float2*)&sWsV[(k + 1) * DD + j0];
            float2 w2 = *(const float2*)&sWsV[(k + 2) * DD + j0];
            float2 w3 = *(const float2*)&sWsV[(k + 3) * DD + j0];
#pragma unroll
            for (int q = 0; q < EPW; q++) {
                float4 x = *(const float4*)(scr + q * SCR + k);
                acc[q][0] += x.x * w0.x; acc[q][1] += x.x * w0.y;
                acc[q][0] += x.y * w1.x; acc[q][1] += x.y * w1.y;
                acc[q][0] += x.z * w2.x; acc[q][1] += x.z * w2.y;
                acc[q][0] += x.w * w3.x; acc[q][1] += x.w * w3.y;
            }
        }
#pragma unroll
        for (int q = 0; q < EPW; q++) {
            float* SM = scr + q * SCR + 52;
            *(float2*)&SM[j0] = make_float2(fmaxf(acc[q][0], 0.f), fmaxf(acc[q][1], 0.f));
        }
        __syncwarp();

        // ---- scatter sm (v4) ----
#pragma unroll
        for (int q = 0; q < EPW; q++) {
            if (lane < 16) {
                const float* SM = scr + q * SCR + 52;
                float4 v = *(const float4*)&SM[lane * 4];
                red_add_v4(&g_aggs[(size_t)sdstw[q] * 64 + lane * 4], v.x, v.y, v.z, v.w);
            }
        }

        if (compute_vm) {
            // ---- Phase 4: gate. lane=(q3, cg) owns cols {cg, cg+4, cg+8, cg+12} ----
            {
                const float* SM = scr + q3 * SCR + 52;
                float a0 = sbg[cg], a1 = sbg[cg + 4], a2 = sbg[cg + 8], a3 = sbg[cg + 12];
#pragma unroll
                for (int j = 0; j < DD; j += 4) {
                    float4 s4 = *(const float4*)&SM[j];
                    float4 w0 = *(const float4*)&sWgT[cg * 68 + j];
                    float4 w1 = *(const float4*)&sWgT[(cg + 4) * 68 + j];
                    float4 w2 = *(const float4*)&sWgT[(cg + 8) * 68 + j];
                    float4 w3 = *(const float4*)&sWgT[(cg + 12) * 68 + j];
                    a0 += s4.x * w0.x + s4.y * w0.y + s4.z * w0.z + s4.w * w0.w;
                    a1 += s4.x * w1.x + s4.y * w1.y + s4.z * w1.z + s4.w * w1.w;
                    a2 += s4.x * w2.x + s4.y * w2.y + s4.z * w2.z + s4.w * w2.w;
                    a3 += s4.x * w3.x + s4.y * w3.y + s4.z * w3.z + s4.w * w3.w;
                }
                float* X = scr + q3 * SCR;
                X[cg]      = 1.f / (1.f + __expf(-a0));
                X[cg + 4]  = 1.f / (1.f + __expf(-a1));
                X[cg + 8]  = 1.f / (1.f + __expf(-a2));
                X[cg + 12] = 1.f / (1.f + __expf(-a3));
            }
            __syncwarp();

            // ---- Phase 5: vm = (Mn[src] + xd*wmux) * gate, direct red.v4 ----
#pragma unroll
            for (int p = 0; p < 4; p++) {
                const int q = 2 * p + hq;
                const float* X = scr + q * SCR;
                const int src = ssrcw[q];
                const int dst = sdstw[q];
                float4 mn = *(const float4*)&g_Mn[(size_t)src * 64 + h16 * 4];
                float x0 = X[48], x1 = X[49], x2 = X[50];
                float gt = X[h16];
                float wm = swmux[h16];
                red_add_v4(&g_aggv[(size_t)dst * 64 + h16 * 4],
                           (mn.x + x0 * wm) * gt,
                           (mn.y + x1 * wm) * gt,
                           (mn.z + x2 * wm) * gt, 0.f);
            }
        }
        __syncwarp();
    }
}

// ---------------- fused update + per-node precompute ----------------
// mode: 0 = init (no residual updates), 1 = mid (update s,v), 2 = last (s only + out)
__global__ __launch_bounds__(256) void update_pre_kernel(
    const float* __restrict__ WsPnext, const float* __restrict__ bsnext,
    const float* __restrict__ Wh, const float* __restrict__ Wmu,
    float* __restrict__ out, int mode, int do_mn)
{
    __shared__ float sW[64 * 64];
    __shared__ float sS[32 * 65];
    __shared__ float sv[32 * 48];
    __shared__ float sVn[32 * 64];
    __shared__ float sWh[16 * 16];
    __shared__ float sWm[16 * 16];

    const int t = threadIdx.x;
    const int nb = blockIdx.x * 32;
    const int nl = t >> 3, j0 = (t & 7) * 8;
    const int node = nb + nl;

    // ---- s path ----
    if (node < NN) {
        float4 s0 = *(const float4*)&g_s[(size_t)node * 64 + j0];
        float4 s1 = *(const float4*)&g_s[(size_t)node * 64 + j0 + 4];
        if (mode != 0) {
            float inv = g_invdeg[node];
            float4 a0 = *(const float4*)&g_aggs[(size_t)node * 64 + j0];
            float4 a1 = *(const float4*)&g_aggs[(size_t)node * 64 + j0 + 4];
            s0.x += a0.x * inv; s0.y += a0.y * inv; s0.z += a0.z * inv; s0.w += a0.w * inv;
            s1.x += a1.x * inv; s1.y += a1.y * inv; s1.z += a1.z * inv; s1.w += a1.w * inv;
            *(float4*)&g_s[(size_t)node * 64 + j0]     = s0;
            *(float4*)&g_s[(size_t)node * 64 + j0 + 4] = s1;
            if (mode == 2) {
                *(float4*)&out[(size_t)node * 64 + j0]     = s0;
                *(float4*)&out[(size_t)node * 64 + j0 + 4] = s1;
            }
        }
        sS[nl * 65 + j0]     = s0.x; sS[nl * 65 + j0 + 1] = s0.y;
        sS[nl * 65 + j0 + 2] = s0.z; sS[nl * 65 + j0 + 3] = s0.w;
        sS[nl * 65 + j0 + 4] = s1.x; sS[nl * 65 + j0 + 5] = s1.y;
        sS[nl * 65 + j0 + 6] = s1.z; sS[nl * 65 + j0 + 7] = s1.w;
    } else {
#pragma unroll
        for (int k = 0; k < 8; k++) sS[nl * 65 + j0 + k] = 0.f;
    }
    if (mode == 2) return;

    // ---- v path ----
    for (int i = t; i < 32 * 48; i += 256) {
        int n2 = i / 48, r = i - n2 * 48;
        int gn = nb + n2;
        float vv = 0.f;
        if (gn < NN) {
            vv = g_v[(size_t)gn * 48 + r];
            if (mode == 1) {
                int o = r / 3, d = r - 3 * o;
                vv += g_aggv[(size_t)gn * 64 + o * 4 + d] * g_invdeg[gn];
                g_v[(size_t)gn * 48 + r] = vv;
            }
        }
        sv[n2 * 48 + r] = vv;
    }

    for (int i = t * 4; i < 64 * 64; i += 1024)
        *(float4*)&sW[i] = *(const float4*)&WsPnext[i];
    if (t < 256) { sWh[t] = Wh[t]; sWm[t] = Wmu[t]; }
    __syncthreads();

    // ---- P GEMM ----
    {
        float4 a0 = *(const float4*)(bsnext + j0);
        float4 a1 = *(const float4*)(bsnext + j0 + 4);
#pragma unroll 8
        for (int k = 0; k < 64; k++) {
            float a = sS[nl * 65 + k];
            float4 w0 = *(const float4*)&sW[k * 64 + j0];
            float4 w1 = *(const float4*)&sW[k * 64 + j0 + 4];
            a0.x += a * w0.x; a0.y += a * w0.y; a0.z += a * w0.z; a0.w += a * w0.w;
            a1.x += a * w1.x; a1.y += a * w1.y; a1.z += a * w1.z; a1.w += a * w1.w;
        }
        if (node < NN) {
            *(float4*)&g_P[(size_t)node * 64 + j0]     = a0;
            *(float4*)&g_P[(size_t)node * 64 + j0 + 4] = a1;
        }
    }

    // ---- Vn = v @ Wh[0:16] ----
    for (int i = t; i < 32 * 48; i += 256) {
        int n = i / 48, r = i - n * 48;
        int h = r / 3, d = r - 3 * h;
        float a = 0.f;
#pragma unroll
        for (int c = 0; c < 16; c++) a += sv[n * 48 + c * 3 + d] * sWh[c * 16 + h];
        sVn[n * 64 + h * 4 + d] = a;
    }
    __syncthreads();

    // ---- nsq + write g_Vn ----
    for (int i = t; i < 32 * 16; i += 256) {
        int n = i >> 4, h = i & 15;
        int gn = nb + n;
        if (gn < NN) {
            float a = sVn[n * 64 + h * 4];
            float b = sVn[n * 64 + h * 4 + 1];
            float c = sVn[n * 64 + h * 4 + 2];
            *(float4*)&g_Vn[(size_t)gn * 64 + h * 4] =
                make_float4(a, b, c, a * a + b * b + c * c);
        }
    }

    // ---- Mn = Vn @ Wmu ----
    if (do_mn) {
        for (int i = t; i < 32 * 48; i += 256) {
            int n = i / 48, r = i - n * 48;
            int o = r / 3, d = r - 3 * o;
            int gn = nb + n;
            if (gn < NN) {
                float a = 0.f;
#pragma unroll
                for (int h = 0; h < 16; h++) a += sVn[n * 64 + h * 4 + d] * sWm[h * 16 + o];
                g_Mn[(size_t)gn * 64 + o * 4 + d] = a;
            }
        }
    }
}

extern "C" void kernel_launch(void* const* d_in, const int* in_sizes, int n_in,
                              void* d_out, int out_size)
{
    const float* sf  = (const float*)d_in[0];
    const float* vf  = (const float*)d_in[2];
    const float* ef  = (const float*)d_in[3];
    const float* xd  = (const float*)d_in[4];
    const float* dv  = (const float*)d_in[5];
    const int*   eix = (const int*)  d_in[6];
    const float* W1  = (const float*)d_in[7];
    const float* b1  = (const float*)d_in[8];
    const float* W2  = (const float*)d_in[9];
    const float* b2  = (const float*)d_in[10];
    const float* Wh  = (const float*)d_in[11];
    const float* Ws  = (const float*)d_in[12];
    const float* bs  = (const float*)d_in[13];
    const float* Wmu = (const float*)d_in[14];
    const float* Wg  = (const float*)d_in[15];
    const float* bg  = (const float*)d_in[16];
    (void)in_sizes; (void)n_in; (void)out_size;

    cudaFuncSetAttribute(edge_kernel,
                         cudaFuncAttributeMaxDynamicSharedMemorySize, SMEM_BYTES);

    void *p_deg = nullptr, *p_aggs = nullptr, *p_aggv = nullptr;
    cudaGetSymbolAddress(&p_deg,  g_deg);
    cudaGetSymbolAddress(&p_aggs, g_aggs);
    cudaGetSymbolAddress(&p_aggv, g_aggv);

    embed_kernel<<<(NN + 7) / 8, 128>>>(sf, W1, b1, W2, b2, vf);
    cudaMemsetAsync(p_deg, 0, NN * sizeof(float));
    deg_kernel<<<(NE + 255) / 256, 256>>>(eix);
    invdeg_kernel<<<(NN + 255) / 256, 256>>>();

    const int nblk = (NN + 31) / 32;
    // init: P0, Vn0, Mn0 (layer-0 weights)
    update_pre_kernel<<<nblk, 256>>>(Ws, bs, Wh, Wmu, nullptr, 0, 1);

    for (int l = 0; l < NLAYER; l++) {
        int vm = (l < NLAYER - 1);
        cudaMemsetAsync(p_aggs, 0, (size_t)NN * 64 * sizeof(float));
        if (vm) cudaMemsetAsync(p_aggv, 0, (size_t)NN * 64 * sizeof(float));
        edge_kernel<<<1184, 256, SMEM_BYTES>>>(
            ef, xd, dv, eix,
            Wh  + l * VCIN * HH,
            Ws  + (size_t)l * 112 * 64 + 64 * 64,
            Wmu + l * HH * VV,
            Wg  + l * DD * VV,
            bg  + l * VV, vm);
        if (l < NLAYER - 1) {
            int ln = l + 1;
            update_pre_kernel<<<nblk, 256>>>(
                Ws + (size_t)ln * 112 * 64, bs + ln * DD,
                Wh + ln * VCIN * HH, Wmu + ln * HH * VV,
                nullptr, 1, (ln < NLAYER - 1) ? 1 : 0);
        } else {
            update_pre_kernel<<<nblk, 256>>>(
                Ws, bs, Wh, Wmu, (float*)d_out, 2, 0);
        }
    }
}

// round 10
// speedup vs baseline: 3.0281x; 1.0994x over previous
#include <cuda_runtime.h>
#include <cuda_bf16.h>

#define S_IN   44
#define HID    128
#define DD     64
#define VV     16
#define HH     16
#define NRBF   16
#define NEF    16
#define VCIN   17
#define NN     50000
#define NE     800000
#define NLAYER 3

typedef unsigned long long u64;

__device__ float g_s[NN * DD];
__device__ float g_v[NN * VV * 3];
__device__ float g_P[NN * DD];        // per-layer: s@Ws[0:64]+bs
__device__ float g_Vn[NN * 64];       // per-layer: [n][h*4 + {x,y,z,nsq}]
__device__ float g_Mn[NN * 64];       // per-layer: [n][o*4 + {x,y,z,-}]
__device__ float g_aggs[NN * DD];
__device__ float g_aggv[NN * 64];     // padded [node][o:16][4]
__device__ float g_deg[NN];
__device__ float g_invdeg[NN];

__device__ __forceinline__ void red_add_v4(float* p, float a, float b, float c, float d)
{
    asm volatile("red.global.add.v4.f32 [%0], {%1,%2,%3,%4};"
                 :: "l"(p), "f"(a), "f"(b), "f"(c), "f"(d) : "memory");
}
__device__ __forceinline__ u64 pack2(float x, float y)
{
    u64 r; asm("mov.b64 %0, {%1, %2};" : "=l"(r) : "f"(x), "f"(y)); return r;
}
__device__ __forceinline__ void unpack2(u64 v, float& x, float& y)
{
    asm("mov.b64 {%0, %1}, %2;" : "=f"(x), "=f"(y) : "l"(v));
}
__device__ __forceinline__ u64 ffma2(u64 a, u64 b, u64 c)
{
    u64 d; asm("fma.rn.f32x2 %0, %1, %2, %3;" : "=l"(d) : "l"(a), "l"(b), "l"(c)); return d;
}

// ---------------- node embedding ----------------
__global__ __launch_bounds__(128) void embed_kernel(
    const float* __restrict__ sf, const float* __restrict__ W1,
    const float* __restrict__ b1, const float* __restrict__ W2,
    const float* __restrict__ b2, const float* __restrict__ vf)
{
    __shared__ float ssf[8][S_IN];
    __shared__ float sh[8][HID];
    const int nb = blockIdx.x * 8;
    const int t  = threadIdx.x;

    for (int i = t; i < 8 * S_IN; i += 128) {
        int n = i / S_IN, k = i - n * S_IN;
        int node = nb + n;
        ssf[n][k] = (node < NN) ? sf[node * S_IN + k] : 0.f;
    }
    __syncthreads();

    float acc[8];
    float bb = b1[t];
#pragma unroll
    for (int n = 0; n < 8; n++) acc[n] = bb;
    for (int k = 0; k < S_IN; k++) {
        float w = W1[k * HID + t];
#pragma unroll
        for (int n = 0; n < 8; n++) acc[n] += ssf[n][k] * w;
    }
#pragma unroll
    for (int n = 0; n < 8; n++) sh[n][t] = fmaxf(acc[n], 0.f);
    __syncthreads();

    if (t < DD) {
        float acc2[8];
        float b2v = b2[t];
#pragma unroll
        for (int n = 0; n < 8; n++) acc2[n] = b2v;
        for (int k = 0; k < HID; k++) {
            float w = W2[k * DD + t];
#pragma unroll
            for (int n = 0; n < 8; n++) acc2[n] += sh[n][k] * w;
        }
#pragma unroll
        for (int n = 0; n < 8; n++)
            if (nb + n < NN) g_s[(nb + n) * DD + t] = acc2[n];
    }
    for (int i = t; i < 8 * VV * 3; i += 128) {
        int n = i / (VV * 3), k = i - n * (VV * 3);
        int node = nb + n;
        if (node < NN) g_v[node * VV * 3 + k] = vf[node * VV * 3 + k];
    }
}

__global__ void deg_kernel(const int* __restrict__ ei)
{
    int e = blockIdx.x * blockDim.x + threadIdx.x;
    if (e < NE) atomicAdd(&g_deg[ei[NE + e]], 1.0f);
}
__global__ void invdeg_kernel()
{
    int i = blockIdx.x * blockDim.x + threadIdx.x;
    if (i < NN) g_invdeg[i] = 1.0f / fmaxf(g_deg[i], 1.0f);
}

// ---------------- edge kernel: warp = 8 edges, f32x2 GEMV ----------------
// per-warp scratch (1104 floats):
//  XI[4 pairs][100]: interleaved X for edge pair (p, p+4):
//     XI[p][k*2+slot], k<48 (0:16 rbf | 16:32 ef | 32:48 vnorm), slot=q>>2
//  SM[8][68] at +400: per-edge sm
//  G [8][20] at +944: per-edge gate[0:16]
#define EPW 8
#define XI_STR 100
#define SM_STR 68
#define G_STR  20
#define WARP_FLTS 1104
#define OFF_WSV  0                       // 48*64 = 3072
#define OFF_WGT  3072                    // 16*68 = 1088 (Wg^T, stride 68)
#define OFF_BG   4160                    // 16
#define OFF_WH16 4176                    // 16
#define OFF_WMUX 4192                    // 16
#define OFF_SRC  4208                    // 64 ints
#define OFF_DST  4272                    // 64 ints
#define OFF_SCR  4336                    // 16B aligned
#define SMEM_FLOATS (OFF_SCR + 8 * WARP_FLTS)
#define SMEM_BYTES  (SMEM_FLOATS * 4)

__global__ __launch_bounds__(256) void edge_kernel(
    const float* __restrict__ ef, const float* __restrict__ xd,
    const float* __restrict__ dvec, const int* __restrict__ ei,
    const float* __restrict__ Wh, const float* __restrict__ WsV,
    const float* __restrict__ Wmu, const float* __restrict__ Wg,
    const float* __restrict__ bg, int compute_vm)
{
    extern __shared__ float smem[];
    float* sWsV  = smem + OFF_WSV;
    float* sWgT  = smem + OFF_WGT;
    float* sbg   = smem + OFF_BG;
    float* swh16 = smem + OFF_WH16;
    float* swmux = smem + OFF_WMUX;

    const int t = threadIdx.x;
    for (int i = t; i < 48 * 64; i += 256) sWsV[i] = WsV[i];
    for (int i = t; i < 16 * 64; i += 256) {
        int j = i >> 4, o = i & 15;            // Wg[j][o]
        sWgT[o * 68 + j] = Wg[i];
    }
    if (t < 16) {
        sbg[t]   = bg[t];
        swh16[t] = Wh[16 * HH + t];
        float a = 0.f;
#pragma unroll
        for (int h = 0; h < HH; h++) a += Wh[16 * HH + h] * Wmu[h * VV + t];
        swmux[t] = a;
    }
    __syncthreads();

    const int warp = t >> 5, lane = t & 31;
    float* scrXI = smem + OFF_SCR + warp * WARP_FLTS;
    float* scrSM = scrXI + 400;
    float* scrG  = scrXI + 944;
    int* ssrcw = (int*)(smem + OFF_SRC) + warp * EPW;
    int* sdstw = (int*)(smem + OFF_DST) + warp * EPW;

    const int hq  = lane >> 4;                  // half-warp id
    const int h16 = lane & 15;                  // h / o role
    const int q3  = lane >> 2, cg = lane & 3;   // gate roles
    const int qe  = lane >> 2;                  // ef role: edge, 4 entries
    const int j0  = 2 * lane;

    const float inv_sigma = (float)NRBF / 10.0f;
    const float mu_step   = 10.0f / (float)(NRBF - 1);

    const int ntiles = NE / (8 * EPW);          // 12500 exact
    for (int tile = blockIdx.x; tile < ntiles; tile += gridDim.x) {
        const int ebase = tile * (8 * EPW) + warp * EPW;

        // ---- Phase 0/1: coalesced loads + staging ----
        if (lane < 8) {
            ssrcw[lane] = ei[ebase + lane];
            sdstw[lane] = ei[NE + ebase + lane];
        }
        float4 efv = *(const float4*)(ef + (size_t)ebase * 16 + lane * 4);
        float xdv = 0.f, dval = 0.f;
        if (lane < 24) xdv = xd[(size_t)ebase * 3 + lane];
        if (lane < 8)  dval = dvec[ebase + lane];
        __syncwarp();

        // ef into XI (4 scalar stores, conflict-free stripes)
        {
            float* xip = scrXI + (qe & 3) * XI_STR;
            int jb = (16 + (lane & 3) * 4) * 2 + (qe >> 2);
            xip[jb]     = efv.x;
            xip[jb + 2] = efv.y;
            xip[jb + 4] = efv.z;
            xip[jb + 6] = efv.w;
        }
        // rbf into XI
#pragma unroll
        for (int p = 0; p < 4; p++) {
            int q = 2 * p + hq;
            float de = __shfl_sync(0xffffffffu, dval, q);
            float tt = (de - (float)h16 * mu_step) * inv_sigma;
            scrXI[(q & 3) * XI_STR + h16 * 2 + (q >> 2)] = __expf(-tt * tt);
        }

        // ---- Phase 2: vnorm from hoisted Vn/nsq ----
#pragma unroll
        for (int p = 0; p < 4; p++) {
            int q = 2 * p + hq;
            int sq = ssrcw[q];
            float4 vn = *(const float4*)&g_Vn[(size_t)sq * 64 + h16 * 4];
            float x0 = __shfl_sync(0xffffffffu, xdv, 3 * q);
            float x1 = __shfl_sync(0xffffffffu, xdv, 3 * q + 1);
            float x2 = __shfl_sync(0xffffffffu, xdv, 3 * q + 2);
            float dot = vn.x * x0 + vn.y * x1 + vn.z * x2;
            float xsq = x0 * x0 + x1 * x1 + x2 * x2;
            float w = swh16[h16];
            scrXI[(q & 3) * XI_STR + (32 + h16) * 2 + (q >> 2)] =
                sqrtf(vn.w + 2.f * w * dot + w * w * xsq + 1e-8f);
        }
        __syncwarp();

        // ---- Phase 3: sm = relu(P[src] + X @ WsV), f32x2 over edge pairs ----
        u64 acc0[4], acc1[4];
        {
            float2 pe[8];
#pragma unroll
            for (int q = 0; q < EPW; q++)
                pe[q] = *(const float2*)&g_P[(size_t)ssrcw[q] * 64 + j0];
#pragma unroll
            for (int p = 0; p < 4; p++) {
                acc0[p] = pack2(pe[p].x, pe[p + 4].x);
                acc1[p] = pack2(pe[p].y, pe[p + 4].y);
            }
        }
#pragma unroll
        for (int k = 0; k < 48; k += 2) {
            float2 w0 = *(const float2*)&sWsV[k * DD + j0];
            float2 w1 = *(const float2*)&sWsV[(k + 1) * DD + j0];
            u64 wx0 = pack2(w0.x, w0.x), wy0 = pack2(w0.y, w0.y);
            u64 wx1 = pack2(w1.x, w1.x), wy1 = pack2(w1.y, w1.y);
#pragma unroll
            for (int p = 0; p < 4; p++) {
                ulonglong2 xx = *(const ulonglong2*)(scrXI + p * XI_STR + k * 2);
                acc0[p] = ffma2(xx.x, wx0, acc0[p]);
                acc1[p] = ffma2(xx.x, wy0, acc1[p]);
                acc0[p] = ffma2(xx.y, wx1, acc0[p]);
                acc1[p] = ffma2(xx.y, wy1, acc1[p]);
            }
        }
#pragma unroll
        for (int p = 0; p < 4; p++) {
            float a, b, c, d;
            unpack2(acc0[p], a, b);   // a: edge p, b: edge p+4 (col j0)
            unpack2(acc1[p], c, d);   // col j0+1
            *(float2*)&scrSM[p * SM_STR + j0] =
                make_float2(fmaxf(a, 0.f), fmaxf(c, 0.f));
            *(float2*)&scrSM[(p + 4) * SM_STR + j0] =
                make_float2(fmaxf(b, 0.f), fmaxf(d, 0.f));
        }
        __syncwarp();

        // ---- scatter sm (v4) ----
#pragma unroll
        for (int q = 0; q < EPW; q++) {
            if (lane < 16) {
                float4 v = *(const float4*)&scrSM[q * SM_STR + lane * 4];
                red_add_v4(&g_aggs[(size_t)sdstw[q] * 64 + lane * 4],
                           v.x, v.y, v.z, v.w);
            }
        }

        if (compute_vm) {
            // ---- Phase 4: gate. lane=(q3, cg) owns cols {cg,cg+4,cg+8,cg+12} ----
            {
                const float* SM = scrSM + q3 * SM_STR;
                float a0 = sbg[cg], a1 = sbg[cg + 4], a2 = sbg[cg + 8], a3 = sbg[cg + 12];
#pragma unroll
                for (int j = 0; j < DD; j += 4) {
                    float4 s4 = *(const float4*)&SM[j];
                    float4 w0 = *(const float4*)&sWgT[cg * 68 + j];
                    float4 w1 = *(const float4*)&sWgT[(cg + 4) * 68 + j];
                    float4 w2 = *(const float4*)&sWgT[(cg + 8) * 68 + j];
                    float4 w3 = *(const float4*)&sWgT[(cg + 12) * 68 + j];
                    a0 += s4.x * w0.x + s4.y * w0.y + s4.z * w0.z + s4.w * w0.w;
                    a1 += s4.x * w1.x + s4.y * w1.y + s4.z * w1.z + s4.w * w1.w;
                    a2 += s4.x * w2.x + s4.y * w2.y + s4.z * w2.z + s4.w * w2.w;
                    a3 += s4.x * w3.x + s4.y * w3.y + s4.z * w3.z + s4.w * w3.w;
                }
                float* G = scrG + q3 * G_STR;
                G[cg]      = 1.f / (1.f + __expf(-a0));
                G[cg + 4]  = 1.f / (1.f + __expf(-a1));
                G[cg + 8]  = 1.f / (1.f + __expf(-a2));
                G[cg + 12] = 1.f / (1.f + __expf(-a3));
            }
            __syncwarp();

            // ---- Phase 5: vm = (Mn[src] + xd*wmux) * gate, direct red.v4 ----
#pragma unroll
            for (int p = 0; p < 4; p++) {
                int q = 2 * p + hq;
                int sq = ssrcw[q], dq = sdstw[q];
                float4 mn = *(const float4*)&g_Mn[(size_t)sq * 64 + h16 * 4];
                float x0 = __shfl_sync(0xffffffffu, xdv, 3 * q);
                float x1 = __shfl_sync(0xffffffffu, xdv, 3 * q + 1);
                float x2 = __shfl_sync(0xffffffffu, xdv, 3 * q + 2);
                float gt = scrG[q * G_STR + h16];
                float wm = swmux[h16];
                red_add_v4(&g_aggv[(size_t)dq * 64 + h16 * 4],
                           (mn.x + x0 * wm) * gt,
                           (mn.y + x1 * wm) * gt,
                           (mn.z + x2 * wm) * gt, 0.f);
            }
        }
        __syncwarp();
    }
}

// ---------------- fused update + per-node precompute ----------------
// mode: 0 = init (no residual updates), 1 = mid (update s,v), 2 = last (s only + out)
__global__ __launch_bounds__(256) void update_pre_kernel(
    const float* __restrict__ WsPnext, const float* __restrict__ bsnext,
    const float* __restrict__ Wh, const float* __restrict__ Wmu,
    float* __restrict__ out, int mode, int do_mn)
{
    __shared__ float sW[64 * 64];
    __shared__ float sS[32 * 65];
    __shared__ float sv[32 * 48];
    __shared__ float sVn[32 * 64];
    __shared__ float sWh[16 * 16];
    __shared__ float sWm[16 * 16];

    const int t = threadIdx.x;
    const int nb = blockIdx.x * 32;
    const int nl = t >> 3, j0 = (t & 7) * 8;
    const int node = nb + nl;

    // ---- s path ----
    if (node < NN) {
        float4 s0 = *(const float4*)&g_s[(size_t)node * 64 + j0];
        float4 s1 = *(const float4*)&g_s[(size_t)node * 64 + j0 + 4];
        if (mode != 0) {
            float inv = g_invdeg[node];
            float4 a0 = *(const float4*)&g_aggs[(size_t)node * 64 + j0];
            float4 a1 = *(const float4*)&g_aggs[(size_t)node * 64 + j0 + 4];
            s0.x += a0.x * inv; s0.y += a0.y * inv; s0.z += a0.z * inv; s0.w += a0.w * inv;
            s1.x += a1.x * inv; s1.y += a1.y * inv; s1.z += a1.z * inv; s1.w += a1.w * inv;
            *(float4*)&g_s[(size_t)node * 64 + j0]     = s0;
            *(float4*)&g_s[(size_t)node * 64 + j0 + 4] = s1;
            if (mode == 2) {
                *(float4*)&out[(size_t)node * 64 + j0]     = s0;
                *(float4*)&out[(size_t)node * 64 + j0 + 4] = s1;
            }
        }
        sS[nl * 65 + j0]     = s0.x; sS[nl * 65 + j0 + 1] = s0.y;
        sS[nl * 65 + j0 + 2] = s0.z; sS[nl * 65 + j0 + 3] = s0.w;
        sS[nl * 65 + j0 + 4] = s1.x; sS[nl * 65 + j0 + 5] = s1.y;
        sS[nl * 65 + j0 + 6] = s1.z; sS[nl * 65 + j0 + 7] = s1.w;
    } else {
#pragma unroll
        for (int k = 0; k < 8; k++) sS[nl * 65 + j0 + k] = 0.f;
    }
    if (mode == 2) return;

    // ---- v path ----
    for (int i = t; i < 32 * 48; i += 256) {
        int n2 = i / 48, r = i - n2 * 48;
        int gn = nb + n2;
        float vv = 0.f;
        if (gn < NN) {
            vv = g_v[(size_t)gn * 48 + r];
            if (mode == 1) {
                int o = r / 3, d = r - 3 * o;
                vv += g_aggv[(size_t)gn * 64 + o * 4 + d] * g_invdeg[gn];
                g_v[(size_t)gn * 48 + r] = vv;
            }
        }
        sv[n2 * 48 + r] = vv;
    }

    for (int i = t * 4; i < 64 * 64; i += 1024)
        *(float4*)&sW[i] = *(const float4*)&WsPnext[i];
    if (t < 256) { sWh[t] = Wh[t]; sWm[t] = Wmu[t]; }
    __syncthreads();

    // ---- P GEMM ----
    {
        float4 a0 = *(const float4*)(bsnext + j0);
        float4 a1 = *(const float4*)(bsnext + j0 + 4);
#pragma unroll 8
        for (int k = 0; k < 64; k++) {
            float a = sS[nl * 65 + k];
            float4 w0 = *(const float4*)&sW[k * 64 + j0];
            float4 w1 = *(const float4*)&sW[k * 64 + j0 + 4];
            a0.x += a * w0.x; a0.y += a * w0.y; a0.z += a * w0.z; a0.w += a * w0.w;
            a1.x += a * w1.x; a1.y += a * w1.y; a1.z += a * w1.z; a1.w += a * w1.w;
        }
        if (node < NN) {
            *(float4*)&g_P[(size_t)node * 64 + j0]     = a0;
            *(float4*)&g_P[(size_t)node * 64 + j0 + 4] = a1;
        }
    }

    // ---- Vn = v @ Wh[0:16] ----
    for (int i = t; i < 32 * 48; i += 256) {
        int n = i / 48, r = i - n * 48;
        int h = r / 3, d = r - 3 * h;
        float a = 0.f;
#pragma unroll
        for (int c = 0; c < 16; c++) a += sv[n * 48 + c * 3 + d] * sWh[c * 16 + h];
        sVn[n * 64 + h * 4 + d] = a;
    }
    __syncthreads();

    // ---- nsq + write g_Vn ----
    for (int i = t; i < 32 * 16; i += 256) {
        int n = i >> 4, h = i & 15;
        int gn = nb + n;
        if (gn < NN) {
            float a = sVn[n * 64 + h * 4];
            float b = sVn[n * 64 + h * 4 + 1];
            float c = sVn[n * 64 + h * 4 + 2];
            *(float4*)&g_Vn[(size_t)gn * 64 + h * 4] =
                make_float4(a, b, c, a * a + b * b + c * c);
        }
    }

    // ---- Mn = Vn @ Wmu ----
    if (do_mn) {
        for (int i = t; i < 32 * 48; i += 256) {
            int n = i / 48, r = i - n * 48;
            int o = r / 3, d = r - 3 * o;
            int gn = nb + n;
            if (gn < NN) {
                float a = 0.f;
#pragma unroll
                for (int h = 0; h < 16; h++) a += sVn[n * 64 + h * 4 + d] * sWm[h * 16 + o];
                g_Mn[(size_t)gn * 64 + o * 4 + d] = a;
            }
        }
    }
}

extern "C" void kernel_launch(void* const* d_in, const int* in_sizes, int n_in,
                              void* d_out, int out_size)
{
    const float* sf  = (const float*)d_in[0];
    const float* vf  = (const float*)d_in[2];
    const float* ef  = (const float*)d_in[3];
    const float* xd  = (const float*)d_in[4];
    const float* dv  = (const float*)d_in[5];
    const int*   eix = (const int*)  d_in[6];
    const float* W1  = (const float*)d_in[7];
    const float* b1  = (const float*)d_in[8];
    const float* W2  = (const float*)d_in[9];
    const float* b2  = (const float*)d_in[10];
    const float* Wh  = (const float*)d_in[11];
    const float* Ws  = (const float*)d_in[12];
    const float* bs  = (const float*)d_in[13];
    const float* Wmu = (const float*)d_in[14];
    const float* Wg  = (const float*)d_in[15];
    const float* bg  = (const float*)d_in[16];
    (void)in_sizes; (void)n_in; (void)out_size;

    cudaFuncSetAttribute(edge_kernel,
                         cudaFuncAttributeMaxDynamicSharedMemorySize, SMEM_BYTES);

    void *p_deg = nullptr, *p_aggs = nullptr, *p_aggv = nullptr;
    cudaGetSymbolAddress(&p_deg,  g_deg);
    cudaGetSymbolAddress(&p_aggs, g_aggs);
    cudaGetSymbolAddress(&p_aggv, g_aggv);

    embed_kernel<<<(NN + 7) / 8, 128>>>(sf, W1, b1, W2, b2, vf);
    cudaMemsetAsync(p_deg, 0, NN * sizeof(float));
    deg_kernel<<<(NE + 255) / 256, 256>>>(eix);
    invdeg_kernel<<<(NN + 255) / 256, 256>>>();

    const int nblk = (NN + 31) / 32;
    // init: P0, Vn0, Mn0 (layer-0 weights)
    update_pre_kernel<<<nblk, 256>>>(Ws, bs, Wh, Wmu, nullptr, 0, 1);

    for (int l = 0; l < NLAYER; l++) {
        int vm = (l < NLAYER - 1);
        cudaMemsetAsync(p_aggs, 0, (size_t)NN * 64 * sizeof(float));
        if (vm) cudaMemsetAsync(p_aggv, 0, (size_t)NN * 64 * sizeof(float));
        edge_kernel<<<1184, 256, SMEM_BYTES>>>(
            ef, xd, dv, eix,
            Wh  + l * VCIN * HH,
            Ws  + (size_t)l * 112 * 64 + 64 * 64,
            Wmu + l * HH * VV,
            Wg  + l * DD * VV,
            bg  + l * VV, vm);
        if (l < NLAYER - 1) {
            int ln = l + 1;
            update_pre_kernel<<<nblk, 256>>>(
                Ws + (size_t)ln * 112 * 64, bs + ln * DD,
                Wh + ln * VCIN * HH, Wmu + ln * HH * VV,
                nullptr, 1, (ln < NLAYER - 1) ? 1 : 0);
        } else {
            update_pre_kernel<<<nblk, 256>>>(
                Ws, bs, Wh, Wmu, (float*)d_out, 2, 0);
        }
    }
}